// round 10
// baseline (speedup 1.0000x reference)
#include <cuda_runtime.h>

#define BS     8
#define NPTS   16384
#define C      32
#define K      256
#define KNN_K  16

typedef unsigned long long ull;

// -------------------- f32x2 packed helpers (Blackwell) --------------------
__device__ __forceinline__ ull pack2(float a, float b) {
    ull r; asm("mov.b64 %0, {%1,%2};" : "=l"(r) : "f"(a), "f"(b)); return r;
}
__device__ __forceinline__ void unpack2(ull v, float& lo, float& hi) {
    asm("mov.b64 {%0,%1}, %2;" : "=f"(lo), "=f"(hi) : "l"(v));
}
__device__ __forceinline__ void fma2(ull& d, ull a, ull b) {
    asm("fma.rn.f32x2 %0, %1, %2, %0;" : "+l"(d) : "l"(a), "l"(b));
}
__device__ __forceinline__ ull add2(ull a, ull b) {
    ull r; asm("add.rn.f32x2 %0, %1, %2;" : "=l"(r) : "l"(a), "l"(b)); return r;
}

// -------------------- scratch (static device arrays) --------------------
__device__ ull g_part2[16 * 128 * 256];   // [(b*2+kblk)][rowblk][jj*4+q]

// ---------------------------------------------------------------------------
// Kernel 1 (frozen at 74.2us): FFMA2 register-tiled GEMM + exp epilogue.
// s[b,n,k] = f[b,n,:]·Wreg[0:32,k]  (pooling-head columns cancel in the
// softmax over n). Block: 128 rows x 128 k. Thread: 8 rows x 4 k-pairs.
// ---------------------------------------------------------------------------
#define SA_STRIDE 260

__global__ void __launch_bounds__(256, 2) regress_gemm_kernel(
    const float* __restrict__ f, const float* __restrict__ posg,
    const float* __restrict__ Wreg)
{
    const int rowblk = blockIdx.x, kblk = blockIdx.y, b = blockIdx.z;
    const int t = threadIdx.x;
    const int tr = t & 15, tk = t >> 4;

    __shared__ float sA[32 * SA_STRIDE];
    __shared__ ull   sW[32 * 64];
    __shared__ float sP[128 * 6];

    const float4* f4 = (const float4*)(f + ((size_t)b * NPTS + rowblk * 128) * C);
#pragma unroll
    for (int i = 0; i < 4; ++i) {
        const int idx = t + i * 256;
        const int r = idx >> 3, c4 = idx & 7;
        const float4 v = f4[idx];
        const int wb = ((r & 7) >> 1) * 64 + (r >> 3) * 4 + (r & 1) * 2;
        ((float2*)(sA + (c4 * 4 + 0) * SA_STRIDE + wb))[0] = make_float2(v.x, v.x);
        ((float2*)(sA + (c4 * 4 + 1) * SA_STRIDE + wb))[0] = make_float2(v.y, v.y);
        ((float2*)(sA + (c4 * 4 + 2) * SA_STRIDE + wb))[0] = make_float2(v.z, v.z);
        ((float2*)(sA + (c4 * 4 + 3) * SA_STRIDE + wb))[0] = make_float2(v.w, v.w);
    }
    for (int i = t; i < 32 * 64; i += 256) {
        const int c = i >> 6, jj = i & 63;
        const float* wp = Wreg + c * K + kblk * 128 + 2 * jj;
        sW[i] = pack2(wp[0], wp[1]);
    }
    const float* pb = posg + ((size_t)b * NPTS + rowblk * 128) * 3;
    for (int i = t; i < 128 * 3; i += 256) {
        const int r = i / 3, d = i - r * 3;
        const float v = pb[i];
        sP[r * 6 + 2 * d] = v; sP[r * 6 + 2 * d + 1] = v;
    }
    __syncthreads();

    ull acc[8][4];
#pragma unroll
    for (int r = 0; r < 8; ++r)
#pragma unroll
        for (int j = 0; j < 4; ++j) acc[r][j] = 0ull;

    const ulonglong2* A2 = (const ulonglong2*)sA;
    const ulonglong2* W2 = (const ulonglong2*)sW;

#pragma unroll 4
    for (int c = 0; c < 32; ++c) {
        const ulonglong2 a0 = A2[c * 65 + 0 * 16 + tr];
        const ulonglong2 a1 = A2[c * 65 + 1 * 16 + tr];
        const ulonglong2 a2 = A2[c * 65 + 2 * 16 + tr];
        const ulonglong2 a3 = A2[c * 65 + 3 * 16 + tr];
        const ulonglong2 w0 = W2[c * 32 + tk * 2 + 0];
        const ulonglong2 w1 = W2[c * 32 + tk * 2 + 1];
        fma2(acc[0][0], a0.x, w0.x); fma2(acc[0][1], a0.x, w0.y);
        fma2(acc[0][2], a0.x, w1.x); fma2(acc[0][3], a0.x, w1.y);
        fma2(acc[1][0], a0.y, w0.x); fma2(acc[1][1], a0.y, w0.y);
        fma2(acc[1][2], a0.y, w1.x); fma2(acc[1][3], a0.y, w1.y);
        fma2(acc[2][0], a1.x, w0.x); fma2(acc[2][1], a1.x, w0.y);
        fma2(acc[2][2], a1.x, w1.x); fma2(acc[2][3], a1.x, w1.y);
        fma2(acc[3][0], a1.y, w0.x); fma2(acc[3][1], a1.y, w0.y);
        fma2(acc[3][2], a1.y, w1.x); fma2(acc[3][3], a1.y, w1.y);
        fma2(acc[4][0], a2.x, w0.x); fma2(acc[4][1], a2.x, w0.y);
        fma2(acc[4][2], a2.x, w1.x); fma2(acc[4][3], a2.x, w1.y);
        fma2(acc[5][0], a2.y, w0.x); fma2(acc[5][1], a2.y, w0.y);
        fma2(acc[5][2], a2.y, w1.x); fma2(acc[5][3], a2.y, w1.y);
        fma2(acc[6][0], a3.x, w0.x); fma2(acc[6][1], a3.x, w0.y);
        fma2(acc[6][2], a3.x, w1.x); fma2(acc[6][3], a3.x, w1.y);
        fma2(acc[7][0], a3.y, w0.x); fma2(acc[7][1], a3.y, w0.y);
        fma2(acc[7][2], a3.y, w1.x); fma2(acc[7][3], a3.y, w1.y);
    }

    ull Qz[4], Qx[4], Qy[4], Qw[4];
#pragma unroll
    for (int j = 0; j < 4; ++j) { Qz[j] = 0; Qx[j] = 0; Qy[j] = 0; Qw[j] = 0; }
    const ull ONE2 = pack2(1.0f, 1.0f);
#pragma unroll
    for (int r = 0; r < 8; ++r) {
        const int rg = tr * 8 + r;
        const ull px2 = *(const ull*)(sP + rg * 6 + 0);
        const ull py2 = *(const ull*)(sP + rg * 6 + 2);
        const ull pz2 = *(const ull*)(sP + rg * 6 + 4);
#pragma unroll
        for (int j = 0; j < 4; ++j) {
            float lo, hi; unpack2(acc[r][j], lo, hi);
            const ull e2 = pack2(__expf(lo), __expf(hi));
            fma2(Qz[j], e2, ONE2);
            fma2(Qx[j], e2, px2);
            fma2(Qy[j], e2, py2);
            fma2(Qw[j], e2, pz2);
        }
    }

    __syncthreads();
    ull* sred = (ull*)sA;
#pragma unroll
    for (int j = 0; j < 4; ++j) {
        const int base = tr * 260 + (tk * 4 + j) * 4;
        sred[base + 0] = Qz[j]; sred[base + 1] = Qx[j];
        sred[base + 2] = Qy[j]; sred[base + 3] = Qw[j];
    }
    __syncthreads();
    ull s = sred[t];
#pragma unroll
    for (int i = 1; i < 16; ++i) s = add2(s, sred[i * 260 + t]);
    g_part2[((size_t)(b * 2 + kblk) * 128 + rowblk) * 256 + t] = s;
}

// ---------------------------------------------------------------------------
// Kernel 2 (fused): keypoint reduce + SPLIT two-pass KNN + gather + GEMV.
// Block = 2 queries x 4 scan-warps (256 thr, 1024 blocks, ~8 warps/SMSP).
// Pass 1 (per scan-warp, 4096-pt slice): per-lane running FMINs -> bitonic ->
//   T_s = 16th-smallest lane-min (>= global 16th). T = min over 4 slices.
// Pass 2: each warp compacts its slice's d2<=T candidates into a shared
//   per-query buffer (shared atomic counter).
// Pass 3 (warp 0 of query): exact lex (d,idx) bitonic selection — identical
//   to jax top_k tie-breaking; buffer order irrelevant to the result.
// ---------------------------------------------------------------------------
#define QPB2  2
#define CCAP  256

__global__ void __launch_bounds__(256) knn_extract_kernel(
    const float* __restrict__ f, const float* __restrict__ posg,
    const float* __restrict__ WE, float* __restrict__ out)
{
    __shared__ float sWE[C * C];
    __shared__ float scd[QPB2][CCAP];
    __shared__ int   sci[QPB2][CCAP];
    __shared__ float sT[QPB2][4];
    __shared__ int   scnt[QPB2];

    const int t = threadIdx.x;
    const int w = t >> 5, lane = t & 31;
    const int q = w >> 2, sw = w & 3;            // query slot, slice
    for (int i = t; i < C * C; i += 256) sWE[i] = WE[i];
    if (t < QPB2) scnt[t] = 0;

    const int pair = blockIdx.x * QPB2 + q;      // QPB2 | 256 -> block shares b
    const int b = pair >> 8;
    const int k = pair & 255;

    // ---- keypoint: sum g_part2 over 128 rowblks (redundant per warp,
    //      identical order -> identical value in all 4 warps)
    const int bf = b * 2 + (k >> 7);
    const int klocal = k & 127;
    const int jj = klocal >> 1, half = klocal & 1;
    const ull* gp = g_part2 + (size_t)bf * 128 * 256 + jj * 4;
    ull sZ = 0, sX = 0, sY = 0, sU = 0;
#pragma unroll
    for (int i = 0; i < 4; ++i) {
        const ull* p = gp + (size_t)(lane + 32 * i) * 256;
        sZ = add2(sZ, p[0]); sX = add2(sX, p[1]);
        sY = add2(sY, p[2]); sU = add2(sU, p[3]);
    }
#pragma unroll
    for (int off = 16; off; off >>= 1) {   // butterfly, deterministic
        sZ = add2(sZ, __shfl_xor_sync(0xffffffffu, sZ, off));
        sX = add2(sX, __shfl_xor_sync(0xffffffffu, sX, off));
        sY = add2(sY, __shfl_xor_sync(0xffffffffu, sY, off));
        sU = add2(sU, __shfl_xor_sync(0xffffffffu, sU, off));
    }
    float Zl, Zh, xl, xh, yl, yh, ul2, uh;
    unpack2(sZ, Zl, Zh); unpack2(sX, xl, xh);
    unpack2(sY, yl, yh); unpack2(sU, ul2, uh);
    const float inv = 1.0f / (half ? Zh : Zl);
    const float kx = (half ? xh : xl) * inv;
    const float ky = (half ? yh : yl) * inv;
    const float kz = (half ? uh : ul2) * inv;

    const float4* pb4 = (const float4*)(posg + (size_t)b * NPTS * 3);
    const float INF = 3.4e38f;

    // ---- pass 1: per-lane running mins over this warp's 4096-pt slice
    float m0 = INF, m1 = INF, m2 = INF, m3 = INF;
#pragma unroll 4
    for (int it = 0; it < 32; ++it) {
        const int p = sw * 1024 + it * 32 + lane;   // point group 4p..4p+3
        const float4 g0 = pb4[3 * p + 0];
        const float4 g1 = pb4[3 * p + 1];
        const float4 g2 = pb4[3 * p + 2];
        float dx, dy, dz;
        dx = g0.x - kx; dy = g0.y - ky; dz = g0.z - kz;
        m0 = fminf(m0, fmaf(dx, dx, fmaf(dy, dy, dz * dz)));
        dx = g0.w - kx; dy = g1.x - ky; dz = g1.y - kz;
        m1 = fminf(m1, fmaf(dx, dx, fmaf(dy, dy, dz * dz)));
        dx = g1.z - kx; dy = g1.w - ky; dz = g2.x - kz;
        m2 = fminf(m2, fmaf(dx, dx, fmaf(dy, dy, dz * dz)));
        dx = g2.y - kx; dy = g2.z - ky; dz = g2.w - kz;
        m3 = fminf(m3, fmaf(dx, dx, fmaf(dy, dy, dz * dz)));
    }
    // bitonic sort 32 lane-minima asc; T_s = lane 15 (>= slice 16th >= global 16th)
    float v = fminf(fminf(m0, m1), fminf(m2, m3));
#pragma unroll
    for (int kk = 2; kk <= 32; kk <<= 1) {
#pragma unroll
        for (int j = kk >> 1; j > 0; j >>= 1) {
            const float o = __shfl_xor_sync(0xffffffffu, v, j);
            const bool asc = ((lane & kk) == 0);
            const bool keepmin = (((lane & j) == 0) == asc);
            v = keepmin ? fminf(v, o) : fmaxf(v, o);
        }
    }
    if (lane == KNN_K - 1) sT[q][sw] = v;
    __syncthreads();

    const float T = fminf(fminf(sT[q][0], sT[q][1]), fminf(sT[q][2], sT[q][3]));

    // ---- pass 2: compact candidates with d2 <= T (shared atomic counter)
    const unsigned lmask = (1u << lane) - 1u;
    for (int it = 0; it < 32; ++it) {
        const int p = sw * 1024 + it * 32 + lane;
        const float4 g0 = pb4[3 * p + 0];
        const float4 g1 = pb4[3 * p + 1];
        const float4 g2 = pb4[3 * p + 2];
        float dx, dy, dz;
        dx = g0.x - kx; dy = g0.y - ky; dz = g0.z - kz;
        const float d0 = fmaf(dx, dx, fmaf(dy, dy, dz * dz));
        dx = g0.w - kx; dy = g1.x - ky; dz = g1.y - kz;
        const float d1 = fmaf(dx, dx, fmaf(dy, dy, dz * dz));
        dx = g1.z - kx; dy = g1.w - ky; dz = g2.x - kz;
        const float d2 = fmaf(dx, dx, fmaf(dy, dy, dz * dz));
        dx = g2.y - kx; dy = g2.z - ky; dz = g2.w - kz;
        const float d3 = fmaf(dx, dx, fmaf(dy, dy, dz * dz));
        const float dmin = fminf(fminf(d0, d1), fminf(d2, d3));
        if (__ballot_sync(0xffffffffu, dmin <= T) == 0u) continue;
        const int pi4 = 4 * p;
        const float dd[4] = {d0, d1, d2, d3};
#pragma unroll
        for (int jc = 0; jc < 4; ++jc) {
            const float dcv = dd[jc];
            const unsigned mm = __ballot_sync(0xffffffffu, dcv <= T);
            if (mm) {
                const int leader = __ffs(mm) - 1;
                int base = 0;
                if (lane == leader) base = atomicAdd(&scnt[q], __popc(mm));
                base = __shfl_sync(0xffffffffu, base, leader);
                if (dcv <= T) {
                    const int o = base + __popc(mm & lmask);
                    if (o < CCAP) { scd[q][o] = dcv; sci[q][o] = pi4 + jc; }
                }
            }
        }
    }
    __syncthreads();

    // ---- pass 3 + gather + GEMV: warp 0 of each query
    if (sw == 0) {
        int cnt = scnt[q]; if (cnt > CCAP) cnt = CCAP;

        float md = (lane < cnt) ? scd[q][lane] : INF;
        int   mi = (lane < cnt) ? sci[q][lane] : 0x7fffffff;
#pragma unroll
        for (int kk = 2; kk <= 32; kk <<= 1) {
#pragma unroll
            for (int j = kk >> 1; j > 0; j >>= 1) {
                const float od = __shfl_xor_sync(0xffffffffu, md, j);
                const int   oi = __shfl_xor_sync(0xffffffffu, mi, j);
                const bool asc = ((lane & kk) == 0);
                const bool low = ((lane & j) == 0);
                const bool oLess = (od < md) || (od == md && oi < mi);
                const bool takeOther = (low == asc) ? oLess : !oLess;
                if (takeOther) { md = od; mi = oi; }
            }
        }
        float mtd = __shfl_sync(0xffffffffu, md, KNN_K - 1);
        int   mti = __shfl_sync(0xffffffffu, mi, KNN_K - 1);

        for (int base0 = 32; base0 < cnt; base0 += 32) {
            const int jjx = base0 + lane;
            float cd2 = (jjx < cnt) ? scd[q][jjx] : INF;
            int   ci2 = (jjx < cnt) ? sci[q][jjx] : 0x7fffffff;
#pragma unroll
            for (int kk = 2; kk <= 32; kk <<= 1) {
#pragma unroll
                for (int j = kk >> 1; j > 0; j >>= 1) {
                    const float od = __shfl_xor_sync(0xffffffffu, cd2, j);
                    const int   oi = __shfl_xor_sync(0xffffffffu, ci2, j);
                    const bool asc = ((lane & kk) == 0);
                    const bool low = ((lane & j) == 0);
                    const bool oLess = (od < cd2) || (od == cd2 && oi < ci2);
                    const bool takeOther = (low == asc) ? oLess : !oLess;
                    if (takeOther) { cd2 = od; ci2 = oi; }
                }
            }
            for (int e = 0; e < 32; ++e) {
                const float dc = __shfl_sync(0xffffffffu, cd2, e);
                const int   ic = __shfl_sync(0xffffffffu, ci2, e);
                if (!(dc < mtd || (dc == mtd && ic < mti))) break; // sorted chunk
                float pd = __shfl_up_sync(0xffffffffu, md, 1);
                int   pi = __shfl_up_sync(0xffffffffu, mi, 1);
                if (lane == 0) { pd = -INF; pi = -1; }
                const bool disp = (dc < md) || (dc == md && ic < mi);
                if (disp) {
                    const bool tp = (pd > dc) || (pd == dc && pi > ic);
                    md = tp ? pd : dc;
                    mi = tp ? pi : ic;
                }
                mtd = __shfl_sync(0xffffffffu, md, KNN_K - 1);
                mti = __shfl_sync(0xffffffffu, mi, KNN_K - 1);
            }
        }

        // gather features of 16 nearest (lanes 0..15), mean, GEMV
        const float* fbase = f + (size_t)b * NPTS * C;
        float acc = 0.f;
#pragma unroll
        for (int r = 0; r < KNN_K; ++r) {
            const int id = __shfl_sync(0xffffffffu, mi, r);
            acc += fbase[(size_t)id * C + lane];
        }
        acc *= (1.0f / KNN_K);

        float o = 0.f;
#pragma unroll
        for (int c = 0; c < C; ++c)
            o = fmaf(__shfl_sync(0xffffffffu, acc, c), sWE[c * C + lane], o);

        out[(size_t)pair * C + lane] = o;
    }
}

// ---------------------------------------------------------------------------
// Inputs: feature, pos, W_pool (dead code — softmax over n cancels the
// per-(b,k)-constant pooled columns), W_regress, W_extract, bs.
// ---------------------------------------------------------------------------
extern "C" void kernel_launch(void* const* d_in, const int* in_sizes, int n_in,
                              void* d_out, int out_size)
{
    (void)in_sizes; (void)n_in; (void)out_size;
    const float* f    = (const float*)d_in[0];
    const float* pos  = (const float*)d_in[1];
    const float* Wreg = (const float*)d_in[3];
    const float* WE   = (const float*)d_in[4];
    float* out = (float*)d_out;

    dim3 g1(NPTS / 128, 2, BS);
    regress_gemm_kernel<<<g1, 256>>>(f, pos, Wreg);
    knn_extract_kernel<<<BS * K / QPB2, 256>>>(f, pos, WE, out);
}

// round 11
// speedup vs baseline: 1.0417x; 1.0417x over previous
#include <cuda_runtime.h>

#define BS     8
#define NPTS   16384
#define C      32
#define K      256
#define KNN_K  16

typedef unsigned long long ull;

// -------------------- f32x2 packed helpers (Blackwell) --------------------
__device__ __forceinline__ ull pack2(float a, float b) {
    ull r; asm("mov.b64 %0, {%1,%2};" : "=l"(r) : "f"(a), "f"(b)); return r;
}
__device__ __forceinline__ void unpack2(ull v, float& lo, float& hi) {
    asm("mov.b64 {%0,%1}, %2;" : "=f"(lo), "=f"(hi) : "l"(v));
}
__device__ __forceinline__ void fma2(ull& d, ull a, ull b) {
    asm("fma.rn.f32x2 %0, %1, %2, %0;" : "+l"(d) : "l"(a), "l"(b));
}
__device__ __forceinline__ ull add2(ull a, ull b) {
    ull r; asm("add.rn.f32x2 %0, %1, %2;" : "=l"(r) : "l"(a), "l"(b)); return r;
}

// -------------------- scratch (static device arrays) --------------------
__device__ ull    g_part2[16 * 128 * 256];   // [(b*2+kblk)][rowblk][jj*4+q]
__device__ float4 g_pos4[BS * NPTS];         // (x, y, z, 0.5*|p|^2)

// ---------------------------------------------------------------------------
// Kernel 0: pack positions with half-squared-norm for the score trick.
// ---------------------------------------------------------------------------
__global__ void pos4_kernel(const float* __restrict__ posg)
{
    const int i = blockIdx.x * blockDim.x + threadIdx.x;   // 0..BS*NPTS-1
    const float x = posg[3 * i + 0];
    const float y = posg[3 * i + 1];
    const float z = posg[3 * i + 2];
    const float hp = 0.5f * fmaf(z, z, fmaf(y, y, x * x));
    g_pos4[i] = make_float4(x, y, z, hp);
}

// ---------------------------------------------------------------------------
// Kernel 1 (frozen at 74.2us): FFMA2 register-tiled GEMM + exp epilogue.
// s[b,n,k] = f[b,n,:]·Wreg[0:32,k]  (pooling-head columns cancel in the
// softmax over n). Block: 128 rows x 128 k. Thread: 8 rows x 4 k-pairs.
// ---------------------------------------------------------------------------
#define SA_STRIDE 260

__global__ void __launch_bounds__(256, 2) regress_gemm_kernel(
    const float* __restrict__ f, const float* __restrict__ posg,
    const float* __restrict__ Wreg)
{
    const int rowblk = blockIdx.x, kblk = blockIdx.y, b = blockIdx.z;
    const int t = threadIdx.x;
    const int tr = t & 15, tk = t >> 4;

    __shared__ float sA[32 * SA_STRIDE];
    __shared__ ull   sW[32 * 64];
    __shared__ float sP[128 * 6];

    const float4* f4 = (const float4*)(f + ((size_t)b * NPTS + rowblk * 128) * C);
#pragma unroll
    for (int i = 0; i < 4; ++i) {
        const int idx = t + i * 256;
        const int r = idx >> 3, c4 = idx & 7;
        const float4 v = f4[idx];
        const int wb = ((r & 7) >> 1) * 64 + (r >> 3) * 4 + (r & 1) * 2;
        ((float2*)(sA + (c4 * 4 + 0) * SA_STRIDE + wb))[0] = make_float2(v.x, v.x);
        ((float2*)(sA + (c4 * 4 + 1) * SA_STRIDE + wb))[0] = make_float2(v.y, v.y);
        ((float2*)(sA + (c4 * 4 + 2) * SA_STRIDE + wb))[0] = make_float2(v.z, v.z);
        ((float2*)(sA + (c4 * 4 + 3) * SA_STRIDE + wb))[0] = make_float2(v.w, v.w);
    }
    for (int i = t; i < 32 * 64; i += 256) {
        const int c = i >> 6, jj = i & 63;
        const float* wp = Wreg + c * K + kblk * 128 + 2 * jj;
        sW[i] = pack2(wp[0], wp[1]);
    }
    const float* pb = posg + ((size_t)b * NPTS + rowblk * 128) * 3;
    for (int i = t; i < 128 * 3; i += 256) {
        const int r = i / 3, d = i - r * 3;
        const float v = pb[i];
        sP[r * 6 + 2 * d] = v; sP[r * 6 + 2 * d + 1] = v;
    }
    __syncthreads();

    ull acc[8][4];
#pragma unroll
    for (int r = 0; r < 8; ++r)
#pragma unroll
        for (int j = 0; j < 4; ++j) acc[r][j] = 0ull;

    const ulonglong2* A2 = (const ulonglong2*)sA;
    const ulonglong2* W2 = (const ulonglong2*)sW;

#pragma unroll 4
    for (int c = 0; c < 32; ++c) {
        const ulonglong2 a0 = A2[c * 65 + 0 * 16 + tr];
        const ulonglong2 a1 = A2[c * 65 + 1 * 16 + tr];
        const ulonglong2 a2 = A2[c * 65 + 2 * 16 + tr];
        const ulonglong2 a3 = A2[c * 65 + 3 * 16 + tr];
        const ulonglong2 w0 = W2[c * 32 + tk * 2 + 0];
        const ulonglong2 w1 = W2[c * 32 + tk * 2 + 1];
        fma2(acc[0][0], a0.x, w0.x); fma2(acc[0][1], a0.x, w0.y);
        fma2(acc[0][2], a0.x, w1.x); fma2(acc[0][3], a0.x, w1.y);
        fma2(acc[1][0], a0.y, w0.x); fma2(acc[1][1], a0.y, w0.y);
        fma2(acc[1][2], a0.y, w1.x); fma2(acc[1][3], a0.y, w1.y);
        fma2(acc[2][0], a1.x, w0.x); fma2(acc[2][1], a1.x, w0.y);
        fma2(acc[2][2], a1.x, w1.x); fma2(acc[2][3], a1.x, w1.y);
        fma2(acc[3][0], a1.y, w0.x); fma2(acc[3][1], a1.y, w0.y);
        fma2(acc[3][2], a1.y, w1.x); fma2(acc[3][3], a1.y, w1.y);
        fma2(acc[4][0], a2.x, w0.x); fma2(acc[4][1], a2.x, w0.y);
        fma2(acc[4][2], a2.x, w1.x); fma2(acc[4][3], a2.x, w1.y);
        fma2(acc[5][0], a2.y, w0.x); fma2(acc[5][1], a2.y, w0.y);
        fma2(acc[5][2], a2.y, w1.x); fma2(acc[5][3], a2.y, w1.y);
        fma2(acc[6][0], a3.x, w0.x); fma2(acc[6][1], a3.x, w0.y);
        fma2(acc[6][2], a3.x, w1.x); fma2(acc[6][3], a3.x, w1.y);
        fma2(acc[7][0], a3.y, w0.x); fma2(acc[7][1], a3.y, w0.y);
        fma2(acc[7][2], a3.y, w1.x); fma2(acc[7][3], a3.y, w1.y);
    }

    ull Qz[4], Qx[4], Qy[4], Qw[4];
#pragma unroll
    for (int j = 0; j < 4; ++j) { Qz[j] = 0; Qx[j] = 0; Qy[j] = 0; Qw[j] = 0; }
    const ull ONE2 = pack2(1.0f, 1.0f);
#pragma unroll
    for (int r = 0; r < 8; ++r) {
        const int rg = tr * 8 + r;
        const ull px2 = *(const ull*)(sP + rg * 6 + 0);
        const ull py2 = *(const ull*)(sP + rg * 6 + 2);
        const ull pz2 = *(const ull*)(sP + rg * 6 + 4);
#pragma unroll
        for (int j = 0; j < 4; ++j) {
            float lo, hi; unpack2(acc[r][j], lo, hi);
            const ull e2 = pack2(__expf(lo), __expf(hi));
            fma2(Qz[j], e2, ONE2);
            fma2(Qx[j], e2, px2);
            fma2(Qy[j], e2, py2);
            fma2(Qw[j], e2, pz2);
        }
    }

    __syncthreads();
    ull* sred = (ull*)sA;
#pragma unroll
    for (int j = 0; j < 4; ++j) {
        const int base = tr * 260 + (tk * 4 + j) * 4;
        sred[base + 0] = Qz[j]; sred[base + 1] = Qx[j];
        sred[base + 2] = Qy[j]; sred[base + 3] = Qw[j];
    }
    __syncthreads();
    ull s = sred[t];
#pragma unroll
    for (int i = 1; i < 16; ++i) s = add2(s, sred[i * 260 + t]);
    g_part2[((size_t)(b * 2 + kblk) * 128 + rowblk) * 256 + t] = s;
}

// ---------------------------------------------------------------------------
// Kernel 2: shared-scan KNN. Block = 128 thr = 4 warps; 4 queries per block.
// Every warp scans ONE 4096-pt slice for ALL 4 queries (load amortized 4x,
// contiguous float4 -> 4 L1 wavefronts per 32 pts instead of 12).
// Score s = 0.5|p|^2 - p.k is rank-equivalent to d2 = 2s + |k|^2.
// Pass 1: per-lane running min of s per query -> bitonic -> per-slice T;
//         T_q = min over slices (>= s of true 16th: 16 smallest lane-mins
//         are s-values of 16 distinct points).
// Pass 2: compact idx of s <= T_q + margin (margin >> float slop ~4e-5
//         between s-ranking and d2-ranking; provably catches all true
//         top-16-by-d2 members).
// Pass 3: warp q recomputes TRUE d2 (same fmaf form validated rounds 1-10)
//         and does exact lex (d2, idx) selection -> identical to top_k.
// ---------------------------------------------------------------------------
#define QPB   4
#define CCAP  192

__global__ void __launch_bounds__(128) knn_extract_kernel(
    const float* __restrict__ f, const float* __restrict__ WE,
    float* __restrict__ out)
{
    __shared__ float sWE[C * C];
    __shared__ int   sci[QPB][CCAP];
    __shared__ float skp[QPB][3];
    __shared__ float sT[QPB][4];
    __shared__ int   scnt[QPB];

    const int t = threadIdx.x;
    const int w = t >> 5, lane = t & 31;          // warp = slice index
    for (int i = t; i < C * C; i += 128) sWE[i] = WE[i];
    if (t < QPB) scnt[t] = 0;

    const int pair0 = blockIdx.x * QPB;           // QPB | 256 -> block shares b
    const int b = pair0 >> 8;

    // ---- keypoints: warp w computes query w's keypoint (once per block)
    {
        const int k = (pair0 + w) & 255;
        const int bf = b * 2 + (k >> 7);
        const int klocal = k & 127;
        const int jj = klocal >> 1, half = klocal & 1;
        const ull* gp = g_part2 + (size_t)bf * 128 * 256 + jj * 4;
        ull sZ = 0, sX = 0, sY = 0, sU = 0;
#pragma unroll
        for (int i = 0; i < 4; ++i) {
            const ull* p = gp + (size_t)(lane + 32 * i) * 256;
            sZ = add2(sZ, p[0]); sX = add2(sX, p[1]);
            sY = add2(sY, p[2]); sU = add2(sU, p[3]);
        }
#pragma unroll
        for (int off = 16; off; off >>= 1) {      // butterfly, deterministic
            sZ = add2(sZ, __shfl_xor_sync(0xffffffffu, sZ, off));
            sX = add2(sX, __shfl_xor_sync(0xffffffffu, sX, off));
            sY = add2(sY, __shfl_xor_sync(0xffffffffu, sY, off));
            sU = add2(sU, __shfl_xor_sync(0xffffffffu, sU, off));
        }
        if (lane == 0) {
            float Zl, Zh, xl, xh, yl, yh, ul2, uh;
            unpack2(sZ, Zl, Zh); unpack2(sX, xl, xh);
            unpack2(sY, yl, yh); unpack2(sU, ul2, uh);
            const float inv = 1.0f / (half ? Zh : Zl);
            skp[w][0] = (half ? xh : xl) * inv;
            skp[w][1] = (half ? yh : yl) * inv;
            skp[w][2] = (half ? uh : ul2) * inv;
        }
    }
    __syncthreads();

    // negated keypoints in registers (for s = fmaf chains)
    float nkx[QPB], nky[QPB], nkz[QPB];
#pragma unroll
    for (int q = 0; q < QPB; ++q) {
        nkx[q] = -skp[q][0]; nky[q] = -skp[q][1]; nkz[q] = -skp[q][2];
    }

    const float4* pp = g_pos4 + (size_t)b * NPTS;
    const float INF = 3.4e38f;

    // ---- pass 1: running min of s per query over this warp's slice
    float m[QPB];
#pragma unroll
    for (int q = 0; q < QPB; ++q) m[q] = INF;
#pragma unroll 4
    for (int it = 0; it < 128; ++it) {
        const int p = (w << 12) + (it << 5) + lane;
        const float4 v = pp[p];
#pragma unroll
        for (int q = 0; q < QPB; ++q) {
            const float s = fmaf(v.z, nkz[q], fmaf(v.y, nky[q],
                              fmaf(v.x, nkx[q], v.w)));
            m[q] = fminf(m[q], s);
        }
    }
#pragma unroll
    for (int q = 0; q < QPB; ++q) {
        float v = m[q];
#pragma unroll
        for (int kk = 2; kk <= 32; kk <<= 1) {
#pragma unroll
            for (int j = kk >> 1; j > 0; j >>= 1) {
                const float o = __shfl_xor_sync(0xffffffffu, v, j);
                const bool asc = ((lane & kk) == 0);
                const bool keepmin = (((lane & j) == 0) == asc);
                v = keepmin ? fminf(v, o) : fmaxf(v, o);
            }
        }
        if (lane == KNN_K - 1) sT[q][w] = v;
    }
    __syncthreads();

    float Te[QPB];
#pragma unroll
    for (int q = 0; q < QPB; ++q) {
        const float T = fminf(fminf(sT[q][0], sT[q][1]),
                              fminf(sT[q][2], sT[q][3]));
        Te[q] = T + 4e-4f + 2e-4f * fabsf(T);   // margin >> slop (~4e-5)
    }

    // ---- pass 2: compact candidate indices (shared atomic counters)
    const unsigned lmask = (1u << lane) - 1u;
#pragma unroll 2
    for (int it = 0; it < 128; ++it) {
        const int p = (w << 12) + (it << 5) + lane;
        const float4 v = pp[p];
        float s[QPB]; bool fq[QPB];
        bool any = false;
#pragma unroll
        for (int q = 0; q < QPB; ++q) {
            s[q] = fmaf(v.z, nkz[q], fmaf(v.y, nky[q],
                      fmaf(v.x, nkx[q], v.w)));
            fq[q] = (s[q] <= Te[q]);
            any |= fq[q];
        }
        if (__ballot_sync(0xffffffffu, any) == 0u) continue;
#pragma unroll
        for (int q = 0; q < QPB; ++q) {
            const unsigned mm = __ballot_sync(0xffffffffu, fq[q]);
            if (mm) {
                const int leader = __ffs(mm) - 1;
                int base = 0;
                if (lane == leader) base = atomicAdd(&scnt[q], __popc(mm));
                base = __shfl_sync(0xffffffffu, base, leader);
                if (fq[q]) {
                    const int o = base + __popc(mm & lmask);
                    if (o < CCAP) sci[q][o] = p;
                }
            }
        }
    }
    __syncthreads();

    // ---- pass 3: warp w does query w — exact d2 lex selection
    {
        const int q = w;
        const int pair = pair0 + q;
        const float kx = skp[q][0], ky = skp[q][1], kz = skp[q][2];
        int cnt = scnt[q]; if (cnt > CCAP) cnt = CCAP;

        float md = INF; int mi = 0x7fffffff;
        if (lane < cnt) {
            mi = sci[q][lane];
            const float4 v = pp[mi];
            const float dx = v.x - kx, dy = v.y - ky, dz = v.z - kz;
            md = fmaf(dx, dx, fmaf(dy, dy, dz * dz));
        }
#pragma unroll
        for (int kk = 2; kk <= 32; kk <<= 1) {
#pragma unroll
            for (int j = kk >> 1; j > 0; j >>= 1) {
                const float od = __shfl_xor_sync(0xffffffffu, md, j);
                const int   oi = __shfl_xor_sync(0xffffffffu, mi, j);
                const bool asc = ((lane & kk) == 0);
                const bool low = ((lane & j) == 0);
                const bool oLess = (od < md) || (od == md && oi < mi);
                const bool takeOther = (low == asc) ? oLess : !oLess;
                if (takeOther) { md = od; mi = oi; }
            }
        }
        float mtd = __shfl_sync(0xffffffffu, md, KNN_K - 1);
        int   mti = __shfl_sync(0xffffffffu, mi, KNN_K - 1);

        for (int base0 = 32; base0 < cnt; base0 += 32) {
            const int jjx = base0 + lane;
            float cd2 = INF; int ci2 = 0x7fffffff;
            if (jjx < cnt) {
                ci2 = sci[q][jjx];
                const float4 v = pp[ci2];
                const float dx = v.x - kx, dy = v.y - ky, dz = v.z - kz;
                cd2 = fmaf(dx, dx, fmaf(dy, dy, dz * dz));
            }
#pragma unroll
            for (int kk = 2; kk <= 32; kk <<= 1) {
#pragma unroll
                for (int j = kk >> 1; j > 0; j >>= 1) {
                    const float od = __shfl_xor_sync(0xffffffffu, cd2, j);
                    const int   oi = __shfl_xor_sync(0xffffffffu, ci2, j);
                    const bool asc = ((lane & kk) == 0);
                    const bool low = ((lane & j) == 0);
                    const bool oLess = (od < cd2) || (od == cd2 && oi < ci2);
                    const bool takeOther = (low == asc) ? oLess : !oLess;
                    if (takeOther) { cd2 = od; ci2 = oi; }
                }
            }
            for (int e = 0; e < 32; ++e) {
                const float dc = __shfl_sync(0xffffffffu, cd2, e);
                const int   ic = __shfl_sync(0xffffffffu, ci2, e);
                if (!(dc < mtd || (dc == mtd && ic < mti))) break;
                float pd = __shfl_up_sync(0xffffffffu, md, 1);
                int   pi = __shfl_up_sync(0xffffffffu, mi, 1);
                if (lane == 0) { pd = -INF; pi = -1; }
                const bool disp = (dc < md) || (dc == md && ic < mi);
                if (disp) {
                    const bool tp = (pd > dc) || (pd == dc && pi > ic);
                    md = tp ? pd : dc;
                    mi = tp ? pi : ic;
                }
                mtd = __shfl_sync(0xffffffffu, md, KNN_K - 1);
                mti = __shfl_sync(0xffffffffu, mi, KNN_K - 1);
            }
        }

        // gather features of 16 nearest (lanes 0..15), mean, GEMV
        const float* fbase = f + (size_t)b * NPTS * C;
        float acc = 0.f;
#pragma unroll
        for (int r = 0; r < KNN_K; ++r) {
            const int id = __shfl_sync(0xffffffffu, mi, r);
            acc += fbase[(size_t)id * C + lane];
        }
        acc *= (1.0f / KNN_K);

        float o = 0.f;
#pragma unroll
        for (int c = 0; c < C; ++c)
            o = fmaf(__shfl_sync(0xffffffffu, acc, c), sWE[c * C + lane], o);

        out[(size_t)pair * C + lane] = o;
    }
}

// ---------------------------------------------------------------------------
// Inputs: feature, pos, W_pool (dead code — softmax over n cancels the
// per-(b,k)-constant pooled columns), W_regress, W_extract, bs.
// ---------------------------------------------------------------------------
extern "C" void kernel_launch(void* const* d_in, const int* in_sizes, int n_in,
                              void* d_out, int out_size)
{
    (void)in_sizes; (void)n_in; (void)out_size;
    const float* f    = (const float*)d_in[0];
    const float* pos  = (const float*)d_in[1];
    const float* Wreg = (const float*)d_in[3];
    const float* WE   = (const float*)d_in[4];
    float* out = (float*)d_out;

    pos4_kernel<<<BS * NPTS / 256, 256>>>(pos);
    dim3 g1(NPTS / 128, 2, BS);
    regress_gemm_kernel<<<g1, 256>>>(f, pos, Wreg);
    knn_extract_kernel<<<BS * K / QPB, 128>>>(f, WE, out);
}

// round 12
// speedup vs baseline: 1.1805x; 1.1333x over previous
#include <cuda_runtime.h>

#define BS     8
#define NPTS   16384
#define C      32
#define K      256
#define KNN_K  16

typedef unsigned long long ull;

// -------------------- f32x2 packed helpers (Blackwell) --------------------
__device__ __forceinline__ ull pack2(float a, float b) {
    ull r; asm("mov.b64 %0, {%1,%2};" : "=l"(r) : "f"(a), "f"(b)); return r;
}
__device__ __forceinline__ void unpack2(ull v, float& lo, float& hi) {
    asm("mov.b64 {%0,%1}, %2;" : "=f"(lo), "=f"(hi) : "l"(v));
}
__device__ __forceinline__ void fma2(ull& d, ull a, ull b) {
    asm("fma.rn.f32x2 %0, %1, %2, %0;" : "+l"(d) : "l"(a), "l"(b));
}
__device__ __forceinline__ ull add2(ull a, ull b) {
    ull r; asm("add.rn.f32x2 %0, %1, %2;" : "=l"(r) : "l"(a), "l"(b)); return r;
}

// -------------------- scratch (static device arrays) --------------------
__device__ ull    g_part2[16 * 128 * 256];   // [(b*2+kblk)][rowblk][jj*4+q]
__device__ float4 g_pos4[BS * NPTS];         // (x, y, z, 0.5*|p|^2)

// ---------------------------------------------------------------------------
// Kernel 1 (frozen at 74.2us): FFMA2 register-tiled GEMM + exp epilogue.
// s[b,n,k] = f[b,n,:]·Wreg[0:32,k]  (pooling-head columns cancel in the
// softmax over n). Block: 128 rows x 128 k. Thread: 8 rows x 4 k-pairs.
// kblk==0 blocks additionally publish g_pos4 (folds the old pos4 kernel).
// ---------------------------------------------------------------------------
#define SA_STRIDE 260

__global__ void __launch_bounds__(256, 2) regress_gemm_kernel(
    const float* __restrict__ f, const float* __restrict__ posg,
    const float* __restrict__ Wreg)
{
    const int rowblk = blockIdx.x, kblk = blockIdx.y, b = blockIdx.z;
    const int t = threadIdx.x;
    const int tr = t & 15, tk = t >> 4;

    __shared__ float sA[32 * SA_STRIDE];
    __shared__ ull   sW[32 * 64];
    __shared__ float sP[128 * 6];

    const float4* f4 = (const float4*)(f + ((size_t)b * NPTS + rowblk * 128) * C);
#pragma unroll
    for (int i = 0; i < 4; ++i) {
        const int idx = t + i * 256;
        const int r = idx >> 3, c4 = idx & 7;
        const float4 v = f4[idx];
        const int wb = ((r & 7) >> 1) * 64 + (r >> 3) * 4 + (r & 1) * 2;
        ((float2*)(sA + (c4 * 4 + 0) * SA_STRIDE + wb))[0] = make_float2(v.x, v.x);
        ((float2*)(sA + (c4 * 4 + 1) * SA_STRIDE + wb))[0] = make_float2(v.y, v.y);
        ((float2*)(sA + (c4 * 4 + 2) * SA_STRIDE + wb))[0] = make_float2(v.z, v.z);
        ((float2*)(sA + (c4 * 4 + 3) * SA_STRIDE + wb))[0] = make_float2(v.w, v.w);
    }
    for (int i = t; i < 32 * 64; i += 256) {
        const int c = i >> 6, jj = i & 63;
        const float* wp = Wreg + c * K + kblk * 128 + 2 * jj;
        sW[i] = pack2(wp[0], wp[1]);
    }
    const float* pb = posg + ((size_t)b * NPTS + rowblk * 128) * 3;
    for (int i = t; i < 128 * 3; i += 256) {
        const int r = i / 3, d = i - r * 3;
        const float v = pb[i];
        sP[r * 6 + 2 * d] = v; sP[r * 6 + 2 * d + 1] = v;
    }
    __syncthreads();

    // fold-in: publish pos4 once (kblk 0 covers every rowblk x b)
    if (kblk == 0 && t < 128) {
        const float x = sP[t * 6 + 0], y = sP[t * 6 + 2], z = sP[t * 6 + 4];
        const float hp = 0.5f * fmaf(z, z, fmaf(y, y, x * x));
        g_pos4[(size_t)b * NPTS + rowblk * 128 + t] = make_float4(x, y, z, hp);
    }

    ull acc[8][4];
#pragma unroll
    for (int r = 0; r < 8; ++r)
#pragma unroll
        for (int j = 0; j < 4; ++j) acc[r][j] = 0ull;

    const ulonglong2* A2 = (const ulonglong2*)sA;
    const ulonglong2* W2 = (const ulonglong2*)sW;

#pragma unroll 4
    for (int c = 0; c < 32; ++c) {
        const ulonglong2 a0 = A2[c * 65 + 0 * 16 + tr];
        const ulonglong2 a1 = A2[c * 65 + 1 * 16 + tr];
        const ulonglong2 a2 = A2[c * 65 + 2 * 16 + tr];
        const ulonglong2 a3 = A2[c * 65 + 3 * 16 + tr];
        const ulonglong2 w0 = W2[c * 32 + tk * 2 + 0];
        const ulonglong2 w1 = W2[c * 32 + tk * 2 + 1];
        fma2(acc[0][0], a0.x, w0.x); fma2(acc[0][1], a0.x, w0.y);
        fma2(acc[0][2], a0.x, w1.x); fma2(acc[0][3], a0.x, w1.y);
        fma2(acc[1][0], a0.y, w0.x); fma2(acc[1][1], a0.y, w0.y);
        fma2(acc[1][2], a0.y, w1.x); fma2(acc[1][3], a0.y, w1.y);
        fma2(acc[2][0], a1.x, w0.x); fma2(acc[2][1], a1.x, w0.y);
        fma2(acc[2][2], a1.x, w1.x); fma2(acc[2][3], a1.x, w1.y);
        fma2(acc[3][0], a1.y, w0.x); fma2(acc[3][1], a1.y, w0.y);
        fma2(acc[3][2], a1.y, w1.x); fma2(acc[3][3], a1.y, w1.y);
        fma2(acc[4][0], a2.x, w0.x); fma2(acc[4][1], a2.x, w0.y);
        fma2(acc[4][2], a2.x, w1.x); fma2(acc[4][3], a2.x, w1.y);
        fma2(acc[5][0], a2.y, w0.x); fma2(acc[5][1], a2.y, w0.y);
        fma2(acc[5][2], a2.y, w1.x); fma2(acc[5][3], a2.y, w1.y);
        fma2(acc[6][0], a3.x, w0.x); fma2(acc[6][1], a3.x, w0.y);
        fma2(acc[6][2], a3.x, w1.x); fma2(acc[6][3], a3.x, w1.y);
        fma2(acc[7][0], a3.y, w0.x); fma2(acc[7][1], a3.y, w0.y);
        fma2(acc[7][2], a3.y, w1.x); fma2(acc[7][3], a3.y, w1.y);
    }

    ull Qz[4], Qx[4], Qy[4], Qw[4];
#pragma unroll
    for (int j = 0; j < 4; ++j) { Qz[j] = 0; Qx[j] = 0; Qy[j] = 0; Qw[j] = 0; }
    const ull ONE2 = pack2(1.0f, 1.0f);
#pragma unroll
    for (int r = 0; r < 8; ++r) {
        const int rg = tr * 8 + r;
        const ull px2 = *(const ull*)(sP + rg * 6 + 0);
        const ull py2 = *(const ull*)(sP + rg * 6 + 2);
        const ull pz2 = *(const ull*)(sP + rg * 6 + 4);
#pragma unroll
        for (int j = 0; j < 4; ++j) {
            float lo, hi; unpack2(acc[r][j], lo, hi);
            const ull e2 = pack2(__expf(lo), __expf(hi));
            fma2(Qz[j], e2, ONE2);
            fma2(Qx[j], e2, px2);
            fma2(Qy[j], e2, py2);
            fma2(Qw[j], e2, pz2);
        }
    }

    __syncthreads();
    ull* sred = (ull*)sA;
#pragma unroll
    for (int j = 0; j < 4; ++j) {
        const int base = tr * 260 + (tk * 4 + j) * 4;
        sred[base + 0] = Qz[j]; sred[base + 1] = Qx[j];
        sred[base + 2] = Qy[j]; sred[base + 3] = Qw[j];
    }
    __syncthreads();
    ull s = sred[t];
#pragma unroll
    for (int i = 1; i < 16; ++i) s = add2(s, sred[i * 260 + t]);
    g_part2[((size_t)(b * 2 + kblk) * 128 + rowblk) * 256 + t] = s;
}

// ---------------------------------------------------------------------------
// Kernel 2: shared-scan KNN. Block = 256 thr = 8 scan-warps; 2 queries/block.
// 1024 blocks -> 8192 warps (~14/SMSP: latency actually hidden) AND 2x load
// sharing with contiguous float4 streams.
// Score s = 0.5|p|^2 - p.k is rank-equivalent to d2 = 2s + |k|^2.
// Pass 1: per-lane running min of s (64 pts/lane) -> per-warp bitonic sort
//   of 32 lane-mins -> publish sorted 16-prefix; warp q merges the 8 sorted
//   prefixes to T = 16th smallest of 256 lane-mins (>= true 16th: lane-mins
//   are s-values of distinct points).
// Pass 2: compact idx of s <= T + margin (margin >> float slop ~4e-5).
// Pass 3: warp q recomputes TRUE d2 and does exact lex (d2, idx) selection
//   -> identical to jax top_k incl. ties. (Validated rounds 9-11.)
// ---------------------------------------------------------------------------
#define QPB   2
#define NW    8
#define SLICE (NPTS / NW)     // 2048
#define CCAP  192

__global__ void __launch_bounds__(256) knn_extract_kernel(
    const float* __restrict__ f, const float* __restrict__ WE,
    float* __restrict__ out)
{
    __shared__ float sWE[C * C];
    __shared__ float sLM[QPB][NW][16];
    __shared__ int   sci[QPB][CCAP];
    __shared__ float skp[QPB][3];
    __shared__ float sTm[QPB];
    __shared__ int   scnt[QPB];

    const int t = threadIdx.x;
    const int w = t >> 5, lane = t & 31;          // warp = slice index
    for (int i = t; i < C * C; i += 256) sWE[i] = WE[i];
    if (t < QPB) scnt[t] = 0;

    const int pair0 = blockIdx.x * QPB;           // QPB | 256 -> block shares b
    const int b = pair0 >> 8;

    // ---- keypoints: warps 0..QPB-1 compute query w's keypoint
    if (w < QPB) {
        const int k = (pair0 + w) & 255;
        const int bf = b * 2 + (k >> 7);
        const int klocal = k & 127;
        const int jj = klocal >> 1, half = klocal & 1;
        const ull* gp = g_part2 + (size_t)bf * 128 * 256 + jj * 4;
        ull sZ = 0, sX = 0, sY = 0, sU = 0;
#pragma unroll
        for (int i = 0; i < 4; ++i) {
            const ull* p = gp + (size_t)(lane + 32 * i) * 256;
            sZ = add2(sZ, p[0]); sX = add2(sX, p[1]);
            sY = add2(sY, p[2]); sU = add2(sU, p[3]);
        }
#pragma unroll
        for (int off = 16; off; off >>= 1) {      // butterfly, deterministic
            sZ = add2(sZ, __shfl_xor_sync(0xffffffffu, sZ, off));
            sX = add2(sX, __shfl_xor_sync(0xffffffffu, sX, off));
            sY = add2(sY, __shfl_xor_sync(0xffffffffu, sY, off));
            sU = add2(sU, __shfl_xor_sync(0xffffffffu, sU, off));
        }
        if (lane == 0) {
            float Zl, Zh, xl, xh, yl, yh, ul2, uh;
            unpack2(sZ, Zl, Zh); unpack2(sX, xl, xh);
            unpack2(sY, yl, yh); unpack2(sU, ul2, uh);
            const float inv = 1.0f / (half ? Zh : Zl);
            skp[w][0] = (half ? xh : xl) * inv;
            skp[w][1] = (half ? yh : yl) * inv;
            skp[w][2] = (half ? uh : ul2) * inv;
        }
    }
    __syncthreads();

    float nkx[QPB], nky[QPB], nkz[QPB];
#pragma unroll
    for (int q = 0; q < QPB; ++q) {
        nkx[q] = -skp[q][0]; nky[q] = -skp[q][1]; nkz[q] = -skp[q][2];
    }

    const float4* pp = g_pos4 + (size_t)b * NPTS;
    const float INF = 3.4e38f;
    const int p0 = w * SLICE;

    // ---- pass 1: running min of s per query; manual x4 unroll for MLP
    float m[QPB];
#pragma unroll
    for (int q = 0; q < QPB; ++q) m[q] = INF;
    for (int it = 0; it < SLICE / 128; ++it) {
        const int pbase = p0 + it * 128 + lane;
        const float4 v0 = pp[pbase +  0];
        const float4 v1 = pp[pbase + 32];
        const float4 v2 = pp[pbase + 64];
        const float4 v3 = pp[pbase + 96];
#pragma unroll
        for (int q = 0; q < QPB; ++q) {
            const float s0 = fmaf(v0.z, nkz[q], fmaf(v0.y, nky[q], fmaf(v0.x, nkx[q], v0.w)));
            const float s1 = fmaf(v1.z, nkz[q], fmaf(v1.y, nky[q], fmaf(v1.x, nkx[q], v1.w)));
            const float s2 = fmaf(v2.z, nkz[q], fmaf(v2.y, nky[q], fmaf(v2.x, nkx[q], v2.w)));
            const float s3 = fmaf(v3.z, nkz[q], fmaf(v3.y, nky[q], fmaf(v3.x, nkx[q], v3.w)));
            m[q] = fminf(m[q], fminf(fminf(s0, s1), fminf(s2, s3)));
        }
    }
#pragma unroll
    for (int q = 0; q < QPB; ++q) {
        float v = m[q];
#pragma unroll
        for (int kk = 2; kk <= 32; kk <<= 1) {
#pragma unroll
            for (int j = kk >> 1; j > 0; j >>= 1) {
                const float o = __shfl_xor_sync(0xffffffffu, v, j);
                const bool asc = ((lane & kk) == 0);
                const bool keepmin = (((lane & j) == 0) == asc);
                v = keepmin ? fminf(v, o) : fmaxf(v, o);
            }
        }
        if (lane < 16) sLM[q][w][lane] = v;   // sorted ascending prefix
    }
    __syncthreads();

    // ---- merge 8 sorted prefixes -> T = 16th smallest of 256 lane-mins
    if (w < QPB) {
        const int q = w;
        float md = (lane < 16) ? sLM[q][0][lane] : INF;
        float mtd = __shfl_sync(0xffffffffu, md, KNN_K - 1);
#pragma unroll
        for (int s = 1; s < NW; ++s) {
            for (int e = 0; e < 16; ++e) {
                const float dc = sLM[q][s][e];       // warp-uniform read
                if (!(dc < mtd)) break;              // sorted input
                float pd = __shfl_up_sync(0xffffffffu, md, 1);
                if (lane == 0) pd = -INF;
                if (dc < md) md = fmaxf(pd, dc);     // sorted shift-insert
                mtd = __shfl_sync(0xffffffffu, md, KNN_K - 1);
            }
        }
        if (lane == 0) sTm[q] = mtd;
    }
    __syncthreads();

    float Te[QPB];
#pragma unroll
    for (int q = 0; q < QPB; ++q)
        Te[q] = sTm[q] + 4e-4f + 2e-4f * fabsf(sTm[q]);  // margin >> slop

    // ---- pass 2: compact candidate indices (shared atomic counters)
    const unsigned lmask = (1u << lane) - 1u;
    for (int it = 0; it < SLICE / 32; ++it) {
        const int p = p0 + it * 32 + lane;
        const float4 v = pp[p];
        float s[QPB]; bool fq[QPB];
        bool any = false;
#pragma unroll
        for (int q = 0; q < QPB; ++q) {
            s[q] = fmaf(v.z, nkz[q], fmaf(v.y, nky[q], fmaf(v.x, nkx[q], v.w)));
            fq[q] = (s[q] <= Te[q]);
            any |= fq[q];
        }
        if (__ballot_sync(0xffffffffu, any) == 0u) continue;
#pragma unroll
        for (int q = 0; q < QPB; ++q) {
            const unsigned mm = __ballot_sync(0xffffffffu, fq[q]);
            if (mm) {
                const int leader = __ffs(mm) - 1;
                int base = 0;
                if (lane == leader) base = atomicAdd(&scnt[q], __popc(mm));
                base = __shfl_sync(0xffffffffu, base, leader);
                if (fq[q]) {
                    const int o = base + __popc(mm & lmask);
                    if (o < CCAP) sci[q][o] = p;
                }
            }
        }
    }
    __syncthreads();

    // ---- pass 3: warps 0..QPB-1 — exact d2 lex selection + gather + GEMV
    if (w < QPB) {
        const int q = w;
        const int pair = pair0 + q;
        const float kx = skp[q][0], ky = skp[q][1], kz = skp[q][2];
        int cnt = scnt[q]; if (cnt > CCAP) cnt = CCAP;

        float md = INF; int mi = 0x7fffffff;
        if (lane < cnt) {
            mi = sci[q][lane];
            const float4 v = pp[mi];
            const float dx = v.x - kx, dy = v.y - ky, dz = v.z - kz;
            md = fmaf(dx, dx, fmaf(dy, dy, dz * dz));
        }
#pragma unroll
        for (int kk = 2; kk <= 32; kk <<= 1) {
#pragma unroll
            for (int j = kk >> 1; j > 0; j >>= 1) {
                const float od = __shfl_xor_sync(0xffffffffu, md, j);
                const int   oi = __shfl_xor_sync(0xffffffffu, mi, j);
                const bool asc = ((lane & kk) == 0);
                const bool low = ((lane & j) == 0);
                const bool oLess = (od < md) || (od == md && oi < mi);
                const bool takeOther = (low == asc) ? oLess : !oLess;
                if (takeOther) { md = od; mi = oi; }
            }
        }
        float mtd = __shfl_sync(0xffffffffu, md, KNN_K - 1);
        int   mti = __shfl_sync(0xffffffffu, mi, KNN_K - 1);

        for (int base0 = 32; base0 < cnt; base0 += 32) {
            const int jjx = base0 + lane;
            float cd2 = INF; int ci2 = 0x7fffffff;
            if (jjx < cnt) {
                ci2 = sci[q][jjx];
                const float4 v = pp[ci2];
                const float dx = v.x - kx, dy = v.y - ky, dz = v.z - kz;
                cd2 = fmaf(dx, dx, fmaf(dy, dy, dz * dz));
            }
#pragma unroll
            for (int kk = 2; kk <= 32; kk <<= 1) {
#pragma unroll
                for (int j = kk >> 1; j > 0; j >>= 1) {
                    const float od = __shfl_xor_sync(0xffffffffu, cd2, j);
                    const int   oi = __shfl_xor_sync(0xffffffffu, ci2, j);
                    const bool asc = ((lane & kk) == 0);
                    const bool low = ((lane & j) == 0);
                    const bool oLess = (od < cd2) || (od == cd2 && oi < ci2);
                    const bool takeOther = (low == asc) ? oLess : !oLess;
                    if (takeOther) { cd2 = od; ci2 = oi; }
                }
            }
            for (int e = 0; e < 32; ++e) {
                const float dc = __shfl_sync(0xffffffffu, cd2, e);
                const int   ic = __shfl_sync(0xffffffffu, ci2, e);
                if (!(dc < mtd || (dc == mtd && ic < mti))) break;
                float pd = __shfl_up_sync(0xffffffffu, md, 1);
                int   pi = __shfl_up_sync(0xffffffffu, mi, 1);
                if (lane == 0) { pd = -INF; pi = -1; }
                const bool disp = (dc < md) || (dc == md && ic < mi);
                if (disp) {
                    const bool tp = (pd > dc) || (pd == dc && pi > ic);
                    md = tp ? pd : dc;
                    mi = tp ? pi : ic;
                }
                mtd = __shfl_sync(0xffffffffu, md, KNN_K - 1);
                mti = __shfl_sync(0xffffffffu, mi, KNN_K - 1);
            }
        }

        // gather features of 16 nearest (lanes 0..15), mean, GEMV
        const float* fbase = f + (size_t)b * NPTS * C;
        float acc = 0.f;
#pragma unroll
        for (int r = 0; r < KNN_K; ++r) {
            const int id = __shfl_sync(0xffffffffu, mi, r);
            acc += fbase[(size_t)id * C + lane];
        }
        acc *= (1.0f / KNN_K);

        float o = 0.f;
#pragma unroll
        for (int c = 0; c < C; ++c)
            o = fmaf(__shfl_sync(0xffffffffu, acc, c), sWE[c * C + lane], o);

        out[(size_t)pair * C + lane] = o;
    }
}

// ---------------------------------------------------------------------------
// Inputs: feature, pos, W_pool (dead code — softmax over n cancels the
// per-(b,k)-constant pooled columns), W_regress, W_extract, bs.
// ---------------------------------------------------------------------------
extern "C" void kernel_launch(void* const* d_in, const int* in_sizes, int n_in,
                              void* d_out, int out_size)
{
    (void)in_sizes; (void)n_in; (void)out_size;
    const float* f    = (const float*)d_in[0];
    const float* pos  = (const float*)d_in[1];
    const float* Wreg = (const float*)d_in[3];
    const float* WE   = (const float*)d_in[4];
    float* out = (float*)d_out;

    dim3 g1(NPTS / 128, 2, BS);
    regress_gemm_kernel<<<g1, 256>>>(f, pos, Wreg);
    knn_extract_kernel<<<BS * K / QPB, 256>>>(f, WE, out);
}

// round 13
// speedup vs baseline: 1.2380x; 1.0487x over previous
#include <cuda_runtime.h>

#define BS     8
#define NPTS   16384
#define C      32
#define K      256
#define KNN_K  16

typedef unsigned long long ull;

// -------------------- f32x2 packed helpers (Blackwell) --------------------
__device__ __forceinline__ ull pack2(float a, float b) {
    ull r; asm("mov.b64 %0, {%1,%2};" : "=l"(r) : "f"(a), "f"(b)); return r;
}
__device__ __forceinline__ void unpack2(ull v, float& lo, float& hi) {
    asm("mov.b64 {%0,%1}, %2;" : "=f"(lo), "=f"(hi) : "l"(v));
}
__device__ __forceinline__ void fma2(ull& d, ull a, ull b) {
    asm("fma.rn.f32x2 %0, %1, %2, %0;" : "+l"(d) : "l"(a), "l"(b));
}
__device__ __forceinline__ ull add2(ull a, ull b) {
    ull r; asm("add.rn.f32x2 %0, %1, %2;" : "=l"(r) : "l"(a), "l"(b)); return r;
}

// -------------------- scratch (static device arrays) --------------------
__device__ ull    g_part2[16 * 128 * 256];   // [(b*2+kblk)][rowblk][jj*4+q]
__device__ float4 g_pos4[BS * NPTS];         // (x, y, z, 0.5*|p|^2)

// ---------------------------------------------------------------------------
// Kernel 1: FFMA2 register-tiled GEMM + exp epilogue.
// s[b,n,k] = f[b,n,:]·Wreg[0:32,k]  (pooling-head columns cancel in the
// softmax over n). Block: 128 rows x 128 k.
// Mapping tr=t>>4 (rows), tk=t&15 (k): A reads are 2-distinct broadcasts
// (1 wf each), W reads are 16-consecutive-ull2 streams from split halves
// (2 wf each) -> 8 smem wf/c-step vs 10 in the R3 layout. Staging identical
// to R3 (no rotation). kblk==0 blocks also publish g_pos4.
// ---------------------------------------------------------------------------
#define SA_STRIDE 260

__global__ void __launch_bounds__(256, 2) regress_gemm_kernel(
    const float* __restrict__ f, const float* __restrict__ posg,
    const float* __restrict__ Wreg)
{
    const int rowblk = blockIdx.x, kblk = blockIdx.y, b = blockIdx.z;
    const int t = threadIdx.x;
    const int tk = t & 15, tr = t >> 4;     // SWAPPED vs R3

    __shared__ float sA[32 * SA_STRIDE];
    __shared__ ull   sW[32 * 64];           // halves: ull [0,1024), [1024,2048)
    __shared__ float sP[128 * 6];

    const float4* f4 = (const float4*)(f + ((size_t)b * NPTS + rowblk * 128) * C);
#pragma unroll
    for (int i = 0; i < 4; ++i) {
        const int idx = t + i * 256;
        const int r = idx >> 3, c4 = idx & 7;
        const float4 v = f4[idx];
        const int wb = ((r & 7) >> 1) * 64 + (r >> 3) * 4 + (r & 1) * 2;
        ((float2*)(sA + (c4 * 4 + 0) * SA_STRIDE + wb))[0] = make_float2(v.x, v.x);
        ((float2*)(sA + (c4 * 4 + 1) * SA_STRIDE + wb))[0] = make_float2(v.y, v.y);
        ((float2*)(sA + (c4 * 4 + 2) * SA_STRIDE + wb))[0] = make_float2(v.z, v.z);
        ((float2*)(sA + (c4 * 4 + 3) * SA_STRIDE + wb))[0] = make_float2(v.w, v.w);
    }
    // split-W staging: half A holds pairs jj=4tkw+{0,1}, half B jj=4tkw+{2,3}
    for (int i = t; i < 32 * 64; i += 256) {
        const int c = i >> 6, jj = i & 63;
        const int tkw = jj >> 2, j = jj & 3;
        const float* wp = Wreg + c * K + kblk * 128 + 2 * jj;
        sW[(j >> 1) * 1024 + (c * 16 + tkw) * 2 + (j & 1)] = pack2(wp[0], wp[1]);
    }
    const float* pb = posg + ((size_t)b * NPTS + rowblk * 128) * 3;
    for (int i = t; i < 128 * 3; i += 256) {
        const int r = i / 3, d = i - r * 3;
        const float v = pb[i];
        sP[r * 6 + 2 * d] = v; sP[r * 6 + 2 * d + 1] = v;
    }
    __syncthreads();

    if (kblk == 0 && t < 128) {
        const float x = sP[t * 6 + 0], y = sP[t * 6 + 2], z = sP[t * 6 + 4];
        const float hp = 0.5f * fmaf(z, z, fmaf(y, y, x * x));
        g_pos4[(size_t)b * NPTS + rowblk * 128 + t] = make_float4(x, y, z, hp);
    }

    ull acc[8][4];
#pragma unroll
    for (int r = 0; r < 8; ++r)
#pragma unroll
        for (int j = 0; j < 4; ++j) acc[r][j] = 0ull;

    const ulonglong2* A2 = (const ulonglong2*)sA;           // c*65 + q*16 + tr
    const ulonglong2* WA = (const ulonglong2*)sW;           // c*16 + tk
    const ulonglong2* WB = (const ulonglong2*)(sW + 1024);  // c*16 + tk

#pragma unroll 4
    for (int c = 0; c < 32; ++c) {
        const ulonglong2 a0 = A2[c * 65 + 0 * 16 + tr];   // rows tr*8+{0,1}
        const ulonglong2 a1 = A2[c * 65 + 1 * 16 + tr];   // rows tr*8+{2,3}
        const ulonglong2 a2 = A2[c * 65 + 2 * 16 + tr];   // rows tr*8+{4,5}
        const ulonglong2 a3 = A2[c * 65 + 3 * 16 + tr];   // rows tr*8+{6,7}
        const ulonglong2 w0 = WA[c * 16 + tk];            // pairs 4tk+{0,1}
        const ulonglong2 w1 = WB[c * 16 + tk];            // pairs 4tk+{2,3}
        fma2(acc[0][0], a0.x, w0.x); fma2(acc[0][1], a0.x, w0.y);
        fma2(acc[0][2], a0.x, w1.x); fma2(acc[0][3], a0.x, w1.y);
        fma2(acc[1][0], a0.y, w0.x); fma2(acc[1][1], a0.y, w0.y);
        fma2(acc[1][2], a0.y, w1.x); fma2(acc[1][3], a0.y, w1.y);
        fma2(acc[2][0], a1.x, w0.x); fma2(acc[2][1], a1.x, w0.y);
        fma2(acc[2][2], a1.x, w1.x); fma2(acc[2][3], a1.x, w1.y);
        fma2(acc[3][0], a1.y, w0.x); fma2(acc[3][1], a1.y, w0.y);
        fma2(acc[3][2], a1.y, w1.x); fma2(acc[3][3], a1.y, w1.y);
        fma2(acc[4][0], a2.x, w0.x); fma2(acc[4][1], a2.x, w0.y);
        fma2(acc[4][2], a2.x, w1.x); fma2(acc[4][3], a2.x, w1.y);
        fma2(acc[5][0], a2.y, w0.x); fma2(acc[5][1], a2.y, w0.y);
        fma2(acc[5][2], a2.y, w1.x); fma2(acc[5][3], a2.y, w1.y);
        fma2(acc[6][0], a3.x, w0.x); fma2(acc[6][1], a3.x, w0.y);
        fma2(acc[6][2], a3.x, w1.x); fma2(acc[6][3], a3.x, w1.y);
        fma2(acc[7][0], a3.y, w0.x); fma2(acc[7][1], a3.y, w0.y);
        fma2(acc[7][2], a3.y, w1.x); fma2(acc[7][3], a3.y, w1.y);
    }

    ull Qz[4], Qx[4], Qy[4], Qw[4];
#pragma unroll
    for (int j = 0; j < 4; ++j) { Qz[j] = 0; Qx[j] = 0; Qy[j] = 0; Qw[j] = 0; }
    const ull ONE2 = pack2(1.0f, 1.0f);
#pragma unroll
    for (int r = 0; r < 8; ++r) {
        const int rg = tr * 8 + r;
        const ull px2 = *(const ull*)(sP + rg * 6 + 0);
        const ull py2 = *(const ull*)(sP + rg * 6 + 2);
        const ull pz2 = *(const ull*)(sP + rg * 6 + 4);
#pragma unroll
        for (int j = 0; j < 4; ++j) {
            float lo, hi; unpack2(acc[r][j], lo, hi);
            const ull e2 = pack2(__expf(lo), __expf(hi));
            fma2(Qz[j], e2, ONE2);
            fma2(Qx[j], e2, px2);
            fma2(Qy[j], e2, py2);
            fma2(Qw[j], e2, pz2);
        }
    }

    __syncthreads();
    ull* sred = (ull*)sA;
#pragma unroll
    for (int j = 0; j < 4; ++j) {
        const int base = tr * 260 + (tk * 4 + j) * 4;   // col = tk*16+j*4+c
        sred[base + 0] = Qz[j]; sred[base + 1] = Qx[j];
        sred[base + 2] = Qy[j]; sred[base + 3] = Qw[j];
    }
    __syncthreads();
    ull s = sred[t];
#pragma unroll
    for (int i = 1; i < 16; ++i) s = add2(s, sred[i * 260 + t]);
    g_part2[((size_t)(b * 2 + kblk) * 128 + rowblk) * 256 + t] = s;
}

// ---------------------------------------------------------------------------
// Kernel 2: shared-scan KNN (R12 structure; pass 2 manually unrolled x4 for
// MLP and 4x fewer ballots). Block = 256 thr = 8 scan-warps; 2 queries/block.
// ---------------------------------------------------------------------------
#define QPB   2
#define NW    8
#define SLICE (NPTS / NW)     // 2048
#define CCAP  192

__global__ void __launch_bounds__(256) knn_extract_kernel(
    const float* __restrict__ f, const float* __restrict__ WE,
    float* __restrict__ out)
{
    __shared__ float sWE[C * C];
    __shared__ float sLM[QPB][NW][16];
    __shared__ int   sci[QPB][CCAP];
    __shared__ float skp[QPB][3];
    __shared__ float sTm[QPB];
    __shared__ int   scnt[QPB];

    const int t = threadIdx.x;
    const int w = t >> 5, lane = t & 31;
    for (int i = t; i < C * C; i += 256) sWE[i] = WE[i];
    if (t < QPB) scnt[t] = 0;

    const int pair0 = blockIdx.x * QPB;
    const int b = pair0 >> 8;

    // ---- keypoints: warps 0..QPB-1 compute query w's keypoint
    if (w < QPB) {
        const int k = (pair0 + w) & 255;
        const int bf = b * 2 + (k >> 7);
        const int klocal = k & 127;
        const int jj = klocal >> 1, half = klocal & 1;
        const ull* gp = g_part2 + (size_t)bf * 128 * 256 + jj * 4;
        ull sZ = 0, sX = 0, sY = 0, sU = 0;
#pragma unroll
        for (int i = 0; i < 4; ++i) {
            const ull* p = gp + (size_t)(lane + 32 * i) * 256;
            sZ = add2(sZ, p[0]); sX = add2(sX, p[1]);
            sY = add2(sY, p[2]); sU = add2(sU, p[3]);
        }
#pragma unroll
        for (int off = 16; off; off >>= 1) {
            sZ = add2(sZ, __shfl_xor_sync(0xffffffffu, sZ, off));
            sX = add2(sX, __shfl_xor_sync(0xffffffffu, sX, off));
            sY = add2(sY, __shfl_xor_sync(0xffffffffu, sY, off));
            sU = add2(sU, __shfl_xor_sync(0xffffffffu, sU, off));
        }
        if (lane == 0) {
            float Zl, Zh, xl, xh, yl, yh, ul2, uh;
            unpack2(sZ, Zl, Zh); unpack2(sX, xl, xh);
            unpack2(sY, yl, yh); unpack2(sU, ul2, uh);
            const float inv = 1.0f / (half ? Zh : Zl);
            skp[w][0] = (half ? xh : xl) * inv;
            skp[w][1] = (half ? yh : yl) * inv;
            skp[w][2] = (half ? uh : ul2) * inv;
        }
    }
    __syncthreads();

    float nkx[QPB], nky[QPB], nkz[QPB];
#pragma unroll
    for (int q = 0; q < QPB; ++q) {
        nkx[q] = -skp[q][0]; nky[q] = -skp[q][1]; nkz[q] = -skp[q][2];
    }

    const float4* pp = g_pos4 + (size_t)b * NPTS;
    const float INF = 3.4e38f;
    const int p0 = w * SLICE;

    // ---- pass 1: running min of s per query; manual x4 unroll for MLP
    float m[QPB];
#pragma unroll
    for (int q = 0; q < QPB; ++q) m[q] = INF;
    for (int it = 0; it < SLICE / 128; ++it) {
        const int pbase = p0 + it * 128 + lane;
        const float4 v0 = pp[pbase +  0];
        const float4 v1 = pp[pbase + 32];
        const float4 v2 = pp[pbase + 64];
        const float4 v3 = pp[pbase + 96];
#pragma unroll
        for (int q = 0; q < QPB; ++q) {
            const float s0 = fmaf(v0.z, nkz[q], fmaf(v0.y, nky[q], fmaf(v0.x, nkx[q], v0.w)));
            const float s1 = fmaf(v1.z, nkz[q], fmaf(v1.y, nky[q], fmaf(v1.x, nkx[q], v1.w)));
            const float s2 = fmaf(v2.z, nkz[q], fmaf(v2.y, nky[q], fmaf(v2.x, nkx[q], v2.w)));
            const float s3 = fmaf(v3.z, nkz[q], fmaf(v3.y, nky[q], fmaf(v3.x, nkx[q], v3.w)));
            m[q] = fminf(m[q], fminf(fminf(s0, s1), fminf(s2, s3)));
        }
    }
#pragma unroll
    for (int q = 0; q < QPB; ++q) {
        float v = m[q];
#pragma unroll
        for (int kk = 2; kk <= 32; kk <<= 1) {
#pragma unroll
            for (int j = kk >> 1; j > 0; j >>= 1) {
                const float o = __shfl_xor_sync(0xffffffffu, v, j);
                const bool asc = ((lane & kk) == 0);
                const bool keepmin = (((lane & j) == 0) == asc);
                v = keepmin ? fminf(v, o) : fmaxf(v, o);
            }
        }
        if (lane < 16) sLM[q][w][lane] = v;
    }
    __syncthreads();

    // ---- merge 8 sorted prefixes -> T = 16th smallest of 256 lane-mins
    if (w < QPB) {
        const int q = w;
        float md = (lane < 16) ? sLM[q][0][lane] : INF;
        float mtd = __shfl_sync(0xffffffffu, md, KNN_K - 1);
#pragma unroll
        for (int s = 1; s < NW; ++s) {
            for (int e = 0; e < 16; ++e) {
                const float dc = sLM[q][s][e];
                if (!(dc < mtd)) break;
                float pd = __shfl_up_sync(0xffffffffu, md, 1);
                if (lane == 0) pd = -INF;
                if (dc < md) md = fmaxf(pd, dc);
                mtd = __shfl_sync(0xffffffffu, md, KNN_K - 1);
            }
        }
        if (lane == 0) sTm[q] = mtd;
    }
    __syncthreads();

    float Te[QPB];
#pragma unroll
    for (int q = 0; q < QPB; ++q)
        Te[q] = sTm[q] + 4e-4f + 2e-4f * fabsf(sTm[q]);

    // ---- pass 2: compaction, manual x4 unroll (4 loads in flight,
    //      one any-ballot per 128 points, compaction ballots only on hits)
    const unsigned lmask = (1u << lane) - 1u;
    for (int it = 0; it < SLICE / 128; ++it) {
        const int p = p0 + it * 128 + lane;
        const float4 v0 = pp[p +  0];
        const float4 v1 = pp[p + 32];
        const float4 v2 = pp[p + 64];
        const float4 v3 = pp[p + 96];
        float s0[QPB], s1[QPB], s2[QPB], s3[QPB];
        bool f0[QPB], f1[QPB], f2[QPB], f3[QPB];
        bool any = false;
#pragma unroll
        for (int q = 0; q < QPB; ++q) {
            s0[q] = fmaf(v0.z, nkz[q], fmaf(v0.y, nky[q], fmaf(v0.x, nkx[q], v0.w)));
            s1[q] = fmaf(v1.z, nkz[q], fmaf(v1.y, nky[q], fmaf(v1.x, nkx[q], v1.w)));
            s2[q] = fmaf(v2.z, nkz[q], fmaf(v2.y, nky[q], fmaf(v2.x, nkx[q], v2.w)));
            s3[q] = fmaf(v3.z, nkz[q], fmaf(v3.y, nky[q], fmaf(v3.x, nkx[q], v3.w)));
            f0[q] = (s0[q] <= Te[q]); f1[q] = (s1[q] <= Te[q]);
            f2[q] = (s2[q] <= Te[q]); f3[q] = (s3[q] <= Te[q]);
            any |= (f0[q] | f1[q] | f2[q] | f3[q]);
        }
        if (__ballot_sync(0xffffffffu, any) == 0u) continue;
#pragma unroll
        for (int q = 0; q < QPB; ++q) {
            const bool fs[4] = {f0[q], f1[q], f2[q], f3[q]};
#pragma unroll
            for (int jc = 0; jc < 4; ++jc) {
                const unsigned mm = __ballot_sync(0xffffffffu, fs[jc]);
                if (mm) {
                    const int leader = __ffs(mm) - 1;
                    int base = 0;
                    if (lane == leader) base = atomicAdd(&scnt[q], __popc(mm));
                    base = __shfl_sync(0xffffffffu, base, leader);
                    if (fs[jc]) {
                        const int o = base + __popc(mm & lmask);
                        if (o < CCAP) sci[q][o] = p + jc * 32;
                    }
                }
            }
        }
    }
    __syncthreads();

    // ---- pass 3: warps 0..QPB-1 — exact d2 lex selection + gather + GEMV
    if (w < QPB) {
        const int q = w;
        const int pair = pair0 + q;
        const float kx = skp[q][0], ky = skp[q][1], kz = skp[q][2];
        int cnt = scnt[q]; if (cnt > CCAP) cnt = CCAP;

        float md = INF; int mi = 0x7fffffff;
        if (lane < cnt) {
            mi = sci[q][lane];
            const float4 v = pp[mi];
            const float dx = v.x - kx, dy = v.y - ky, dz = v.z - kz;
            md = fmaf(dx, dx, fmaf(dy, dy, dz * dz));
        }
#pragma unroll
        for (int kk = 2; kk <= 32; kk <<= 1) {
#pragma unroll
            for (int j = kk >> 1; j > 0; j >>= 1) {
                const float od = __shfl_xor_sync(0xffffffffu, md, j);
                const int   oi = __shfl_xor_sync(0xffffffffu, mi, j);
                const bool asc = ((lane & kk) == 0);
                const bool low = ((lane & j) == 0);
                const bool oLess = (od < md) || (od == md && oi < mi);
                const bool takeOther = (low == asc) ? oLess : !oLess;
                if (takeOther) { md = od; mi = oi; }
            }
        }
        float mtd = __shfl_sync(0xffffffffu, md, KNN_K - 1);
        int   mti = __shfl_sync(0xffffffffu, mi, KNN_K - 1);

        for (int base0 = 32; base0 < cnt; base0 += 32) {
            const int jjx = base0 + lane;
            float cd2 = INF; int ci2 = 0x7fffffff;
            if (jjx < cnt) {
                ci2 = sci[q][jjx];
                const float4 v = pp[ci2];
                const float dx = v.x - kx, dy = v.y - ky, dz = v.z - kz;
                cd2 = fmaf(dx, dx, fmaf(dy, dy, dz * dz));
            }
#pragma unroll
            for (int kk = 2; kk <= 32; kk <<= 1) {
#pragma unroll
                for (int j = kk >> 1; j > 0; j >>= 1) {
                    const float od = __shfl_xor_sync(0xffffffffu, cd2, j);
                    const int   oi = __shfl_xor_sync(0xffffffffu, ci2, j);
                    const bool asc = ((lane & kk) == 0);
                    const bool low = ((lane & j) == 0);
                    const bool oLess = (od < cd2) || (od == cd2 && oi < ci2);
                    const bool takeOther = (low == asc) ? oLess : !oLess;
                    if (takeOther) { cd2 = od; ci2 = oi; }
                }
            }
            for (int e = 0; e < 32; ++e) {
                const float dc = __shfl_sync(0xffffffffu, cd2, e);
                const int   ic = __shfl_sync(0xffffffffu, ci2, e);
                if (!(dc < mtd || (dc == mtd && ic < mti))) break;
                float pd = __shfl_up_sync(0xffffffffu, md, 1);
                int   pi = __shfl_up_sync(0xffffffffu, mi, 1);
                if (lane == 0) { pd = -INF; pi = -1; }
                const bool disp = (dc < md) || (dc == md && ic < mi);
                if (disp) {
                    const bool tp = (pd > dc) || (pd == dc && pi > ic);
                    md = tp ? pd : dc;
                    mi = tp ? pi : ic;
                }
                mtd = __shfl_sync(0xffffffffu, md, KNN_K - 1);
                mti = __shfl_sync(0xffffffffu, mi, KNN_K - 1);
            }
        }

        // gather features of 16 nearest (lanes 0..15), mean, GEMV
        const float* fbase = f + (size_t)b * NPTS * C;
        float acc = 0.f;
#pragma unroll
        for (int r = 0; r < KNN_K; ++r) {
            const int id = __shfl_sync(0xffffffffu, mi, r);
            acc += fbase[(size_t)id * C + lane];
        }
        acc *= (1.0f / KNN_K);

        float o = 0.f;
#pragma unroll
        for (int c = 0; c < C; ++c)
            o = fmaf(__shfl_sync(0xffffffffu, acc, c), sWE[c * C + lane], o);

        out[(size_t)pair * C + lane] = o;
    }
}

// ---------------------------------------------------------------------------
// Inputs: feature, pos, W_pool (dead code — softmax over n cancels the
// per-(b,k)-constant pooled columns), W_regress, W_extract, bs.
// ---------------------------------------------------------------------------
extern "C" void kernel_launch(void* const* d_in, const int* in_sizes, int n_in,
                              void* d_out, int out_size)
{
    (void)in_sizes; (void)n_in; (void)out_size;
    const float* f    = (const float*)d_in[0];
    const float* pos  = (const float*)d_in[1];
    const float* Wreg = (const float*)d_in[3];
    const float* WE   = (const float*)d_in[4];
    float* out = (float*)d_out;

    dim3 g1(NPTS / 128, 2, BS);
    regress_gemm_kernel<<<g1, 256>>>(f, pos, Wreg);
    knn_extract_kernel<<<BS * K / QPB, 256>>>(f, WE, out);
}

// round 16
// speedup vs baseline: 1.6711x; 1.3498x over previous
#include <cuda_runtime.h>
#include <cuda_bf16.h>

#define BS     8
#define NPTS   16384
#define C      32
#define K      256
#define KNN_K  16

typedef unsigned long long ull;

// Arch-specific dispatch: tcgen05 only exists in the sm_103a cubin; the
// compute_103 PTX stage (and any JIT fallback) gets the proven FFMA2 path.
// NOTE: only CODE may be guarded — no __device__ objects inside the guard
// (their host-stub registration is unconditional -> link error, see R15).
#if defined(__CUDA_ARCH_FEAT_SM103_ALL)
#define TC_PATH 1
#else
#define TC_PATH 0
#endif

// -------------------- f32x2 packed helpers --------------------
__device__ __forceinline__ ull pack2(float a, float b) {
    ull r; asm("mov.b64 %0, {%1,%2};" : "=l"(r) : "f"(a), "f"(b)); return r;
}
__device__ __forceinline__ void unpack2(ull v, float& lo, float& hi) {
    asm("mov.b64 {%0,%1}, %2;" : "=f"(lo), "=f"(hi) : "l"(v));
}
__device__ __forceinline__ void fma2(ull& d, ull a, ull b) {
    asm("fma.rn.f32x2 %0, %1, %2, %0;" : "+l"(d) : "l"(a), "l"(b));
}
__device__ __forceinline__ ull add2(ull a, ull b) {
    ull r; asm("add.rn.f32x2 %0, %1, %2;" : "=l"(r) : "l"(a), "l"(b)); return r;
}
__device__ __forceinline__ unsigned smem_u32(const void* p) {
    unsigned a;
    asm("{ .reg .u64 t; cvta.to.shared.u64 t, %1; cvt.u32.u64 %0, t; }"
        : "=r"(a) : "l"(p));
    return a;
}
#define SW128(off) ((off) ^ (((off) >> 3) & 0x70))

// SW128 descriptor base (layout=2, version=1, SBO=64, LBO=1) — preprocessor
// constant only, nothing registered host-side.
#define SMEM_DESC_BASE_ULL ((2ull << 61) | (1ull << 46) | (64ull << 32) | (1ull << 16))

// -------------------- scratch (static device arrays, unconditional) -------
__device__ ull    g_part2[16 * 128 * 256];   // fallback partials
__device__ float4 g_part3[16 * 256 * 128];   // tcgen05 partials
__device__ float4 g_pos4[BS * NPTS];         // (x, y, z, 0.5*|p|^2)

// ---------------------------------------------------------------------------
// tcgen05-only PTX wrappers (compiled only in the sm_103a cubin)
// ---------------------------------------------------------------------------
#if TC_PATH
__device__ __forceinline__ unsigned elect_one() {
    unsigned p;
    asm volatile("{ .reg .pred p; elect.sync _|p, 0xFFFFFFFF; selp.b32 %0, 1, 0, p; }"
                 : "=r"(p));
    return p;
}
__device__ __forceinline__ ull make_desc(unsigned smem_addr) {
    return SMEM_DESC_BASE_ULL | ((ull)(smem_addr >> 4) & 0x3FFF);
}
__device__ __forceinline__ void mma_f16_ss_cg1(
    unsigned d_tmem, ull a_desc, ull b_desc, unsigned idesc, unsigned en)
{
    asm volatile(
        "{\n\t.reg .pred p;\n\tsetp.ne.u32 p, %5, 0;\n\t"
        "tcgen05.mma.cta_group::1.kind::f16 [%0], %1, %2, %3, {%4,%4,%4,%4}, p;\n\t}"
        :: "r"(d_tmem), "l"(a_desc), "l"(b_desc), "r"(idesc), "r"(0u), "r"(en)
        : "memory");
}
#define TC_ALLOC(sm, n)  asm volatile("tcgen05.alloc.cta_group::1.sync.aligned.shared::cta.b32 [%0], %1;" :: "r"(sm), "r"(n) : "memory")
#define TC_DEALLOC(tm,n) asm volatile("tcgen05.dealloc.cta_group::1.sync.aligned.b32 %0, %1;" :: "r"(tm), "r"(n))
#define TC_RELINQ()      asm volatile("tcgen05.relinquish_alloc_permit.cta_group::1.sync.aligned;")
#define TC_COMMIT(mb)    asm volatile("tcgen05.commit.cta_group::1.mbarrier::arrive::one.shared::cluster.b64 [%0];" :: "r"(mb) : "memory")
#define TC_FENCE_AFTER() asm volatile("tcgen05.fence::after_thread_sync;" ::: "memory")
#define TC_WAIT_LD()     asm volatile("tcgen05.wait::ld.sync.aligned;" ::: "memory")
#define FENCE_ASYNC()    asm volatile("fence.proxy.async.shared::cta;" ::: "memory")
#define MBAR_INIT(mb,c)  asm volatile("mbarrier.init.shared.b64 [%0], %1;" :: "r"(mb), "r"(c) : "memory")
#define MBAR_INVAL(mb)   asm volatile("mbarrier.inval.shared.b64 [%0];" :: "r"(mb) : "memory")
#define MBAR_WAIT(mb, ph) do { \
    unsigned _mb = (mb), _ph = (ph), _done; \
    asm volatile("{\n\t.reg .pred p;\n\tmbarrier.try_wait.parity.acquire.cta.shared::cta.b64 p, [%1], %2;\n\tselp.b32 %0, 1, 0, p;\n\t}" \
        : "=r"(_done) : "r"(_mb), "r"(_ph) : "memory"); \
    if (!_done) { \
        asm volatile("{\n\t.reg .pred P1;\n\tWL_%=:\n\tmbarrier.try_wait.parity.acquire.cta.shared::cta.b64 P1, [%0], %1, 0x989680;\n\t@P1 bra.uni WD_%=;\n\tbra.uni WL_%=;\n\tWD_%=:\n\t}" \
            :: "r"(_mb), "r"(_ph) : "memory"); \
    } \
} while (0)
#define LDTM_X32(r, a) \
    asm volatile("tcgen05.ld.sync.aligned.32x32b.x32.b32 " \
        "{%0,%1,%2,%3,%4,%5,%6,%7,%8,%9,%10,%11,%12,%13,%14,%15," \
        "%16,%17,%18,%19,%20,%21,%22,%23,%24,%25,%26,%27,%28,%29,%30,%31}, [%32];" \
        : "=r"((r)[0]),"=r"((r)[1]),"=r"((r)[2]),"=r"((r)[3]),"=r"((r)[4]),"=r"((r)[5]),"=r"((r)[6]),"=r"((r)[7]), \
          "=r"((r)[8]),"=r"((r)[9]),"=r"((r)[10]),"=r"((r)[11]),"=r"((r)[12]),"=r"((r)[13]),"=r"((r)[14]),"=r"((r)[15]), \
          "=r"((r)[16]),"=r"((r)[17]),"=r"((r)[18]),"=r"((r)[19]),"=r"((r)[20]),"=r"((r)[21]),"=r"((r)[22]),"=r"((r)[23]), \
          "=r"((r)[24]),"=r"((r)[25]),"=r"((r)[26]),"=r"((r)[27]),"=r"((r)[28]),"=r"((r)[29]),"=r"((r)[30]),"=r"((r)[31]) \
        : "r"(a))
#endif

// tcgen05-path smem layout (dynamic)
#define TILE_A   0
#define TILE_B   16384
#define TILE_3   32768
#define OFF_POS  49152     // float4[128] block-local positions
#define OFF_TPTR 51200
#define OFF_MBAR 51208
#define SMEM_DYN 51264
#define MMA_IDESC 0x8200490u   // F32 acc, bf16 x bf16, M=128, N=128

#define SA_STRIDE 260

// ---------------------------------------------------------------------------
// Kernel 1: s[b,n,k] = f[b,n,:]·Wreg[0:32,k] (pooling head cancels in the
// softmax over n) + exp epilogue -> partial (Z, wx, wy, wz).
// TC_PATH: S^T via bf16 triple-split SS tcgen05 MMA (fp32 TMEM accumulate);
// else: the proven R13 FFMA2 register-tiled GEMM.
// Grid (128 rowblk, 2 kblk, 8 b), 256 threads.
// ---------------------------------------------------------------------------
__global__ void __launch_bounds__(256, 2) regress_kernel(
    const float* __restrict__ f, const float* __restrict__ posg,
    const float* __restrict__ Wreg)
{
#if TC_PATH
    extern __shared__ char smem[];
    const unsigned sbase = smem_u32(smem);
    const int rowblk = blockIdx.x, kblk = blockIdx.y, b = blockIdx.z;
    const int t = threadIdx.x;
    const int w = t >> 5, lane = t & 31;

    if (w == 0) { TC_ALLOC(sbase + OFF_TPTR, 128); TC_RELINQ(); }
    if (t == 0) MBAR_INIT(sbase + OFF_MBAR, 1);

    // ---- stage B = F tile [n=128 rows, c=32], bf16 triple split
    {
        const float* fb = f + ((size_t)b * NPTS + rowblk * 128) * C;
#pragma unroll
        for (int i = 0; i < 16; ++i) {
            const int idx = t + i * 256;
            const int row = idx >> 5, c = idx & 31;
            const float v = fb[idx];
            const __nv_bfloat16 h1 = __float2bfloat16_rn(v);
            const float r1 = v - __bfloat162float(h1);
            const __nv_bfloat16 h2 = __float2bfloat16_rn(r1);
            const float r2 = r1 - __bfloat162float(h2);
            const __nv_bfloat16 h3 = __float2bfloat16_rn(r2);
            const int base = row * 128 + c * 2;
            *(__nv_bfloat16*)(smem + TILE_B + SW128(base))      = h1;
            *(__nv_bfloat16*)(smem + TILE_B + SW128(base + 64)) = h2;
            *(__nv_bfloat16*)(smem + TILE_3 + SW128(base + 64)) = h3;
        }
    }
    // ---- stage A = W^T tile [k=128 rows, c=32], bf16 triple split
    {
#pragma unroll
        for (int i = 0; i < 16; ++i) {
            const int idx = t + i * 256;
            const int row = idx >> 5, c = idx & 31;
            const float v = Wreg[c * K + kblk * 128 + row];
            const __nv_bfloat16 h1 = __float2bfloat16_rn(v);
            const float r1 = v - __bfloat162float(h1);
            const __nv_bfloat16 h2 = __float2bfloat16_rn(r1);
            const float r2 = r1 - __bfloat162float(h2);
            const __nv_bfloat16 h3 = __float2bfloat16_rn(r2);
            const int base = row * 128 + c * 2;
            *(__nv_bfloat16*)(smem + TILE_A + SW128(base))      = h1;
            *(__nv_bfloat16*)(smem + TILE_A + SW128(base + 64)) = h2;
            *(__nv_bfloat16*)(smem + TILE_3 + SW128(base))      = h3;
        }
    }
    // ---- stage positions block-locally (race-free); publish g_pos4 once
    if (t < 128) {
        const float* pr = posg + ((size_t)b * NPTS + rowblk * 128 + t) * 3;
        const float x = pr[0], y = pr[1], z = pr[2];
        const float hp = 0.5f * fmaf(z, z, fmaf(y, y, x * x));
        ((float4*)(smem + OFF_POS))[t] = make_float4(x, y, z, hp);
        if (kblk == 0)
            g_pos4[(size_t)b * NPTS + rowblk * 128 + t] = make_float4(x, y, z, hp);
    }
    FENCE_ASYNC();
    __syncthreads();

    unsigned tmem;
    asm volatile("ld.shared.b32 %0, [%1];" : "=r"(tmem) : "r"(sbase + OFF_TPTR));

    if (w == 0 && elect_one()) {
        const ull dA = make_desc(sbase + TILE_A);
        const ull dB = make_desc(sbase + TILE_B);
        const ull d3 = make_desc(sbase + TILE_3);
        mma_f16_ss_cg1(tmem, dA + 0, dB + 0, MMA_IDESC, 0);  // a1b1
        mma_f16_ss_cg1(tmem, dA + 2, dB + 2, MMA_IDESC, 1);
        mma_f16_ss_cg1(tmem, dA + 0, dB + 4, MMA_IDESC, 1);  // a1b2
        mma_f16_ss_cg1(tmem, dA + 2, dB + 6, MMA_IDESC, 1);
        mma_f16_ss_cg1(tmem, dA + 4, dB + 0, MMA_IDESC, 1);  // a2b1
        mma_f16_ss_cg1(tmem, dA + 6, dB + 2, MMA_IDESC, 1);
        mma_f16_ss_cg1(tmem, dA + 0, d3 + 4, MMA_IDESC, 1);  // a1b3
        mma_f16_ss_cg1(tmem, dA + 2, d3 + 6, MMA_IDESC, 1);
        mma_f16_ss_cg1(tmem, dA + 4, dB + 4, MMA_IDESC, 1);  // a2b2
        mma_f16_ss_cg1(tmem, dA + 6, dB + 6, MMA_IDESC, 1);
        mma_f16_ss_cg1(tmem, d3 + 0, dB + 0, MMA_IDESC, 1);  // a3b1
        mma_f16_ss_cg1(tmem, d3 + 2, dB + 2, MMA_IDESC, 1);
        TC_COMMIT(sbase + OFF_MBAR);
    }
    __syncthreads();
    MBAR_WAIT(sbase + OFF_MBAR, 0);
    TC_FENCE_AFTER();

    // ---- epilogue: warp w reads its subpartition (lanes = k), cols = n
    const int half = w >> 2;
    const int nbase = half * 64;
    const float4* pp = (const float4*)(smem + OFF_POS) + nbase;
    float Qz = 0.f, Qx = 0.f, Qy = 0.f, Qw = 0.f;
#pragma unroll
    for (int ch = 0; ch < 2; ++ch) {
        unsigned dr[32];
        LDTM_X32(dr, tmem + nbase + ch * 32);
        TC_WAIT_LD();
#pragma unroll
        for (int j = 0; j < 32; ++j) {
            const float4 p = pp[ch * 32 + j];   // smem uniform broadcast
            const float e = __expf(__uint_as_float(dr[j]));
            Qz += e;
            Qx = fmaf(e, p.x, Qx);
            Qy = fmaf(e, p.y, Qy);
            Qw = fmaf(e, p.z, Qw);
        }
    }
    {
        const int bf = b * 2 + kblk;
        const int klane = (w & 3) * 32 + lane;
        g_part3[((size_t)(bf * 128 + rowblk) * 2 + half) * 128 + klane] =
            make_float4(Qz, Qx, Qy, Qw);
    }
    __syncthreads();
    if (t == 0) MBAR_INVAL(sbase + OFF_MBAR);
    __syncthreads();
    if (w == 0) TC_DEALLOC(tmem, 128);

#else  // ---------------- fallback: R13 FFMA2 path (proven) ----------------
    const int rowblk = blockIdx.x, kblk = blockIdx.y, b = blockIdx.z;
    const int t = threadIdx.x;
    const int tk = t & 15, tr = t >> 4;

    __shared__ float sA[32 * SA_STRIDE];
    __shared__ ull   sW[32 * 64];
    __shared__ float sP[128 * 6];

    const float4* f4 = (const float4*)(f + ((size_t)b * NPTS + rowblk * 128) * C);
#pragma unroll
    for (int i = 0; i < 4; ++i) {
        const int idx = t + i * 256;
        const int r = idx >> 3, c4 = idx & 7;
        const float4 v = f4[idx];
        const int wb = ((r & 7) >> 1) * 64 + (r >> 3) * 4 + (r & 1) * 2;
        ((float2*)(sA + (c4 * 4 + 0) * SA_STRIDE + wb))[0] = make_float2(v.x, v.x);
        ((float2*)(sA + (c4 * 4 + 1) * SA_STRIDE + wb))[0] = make_float2(v.y, v.y);
        ((float2*)(sA + (c4 * 4 + 2) * SA_STRIDE + wb))[0] = make_float2(v.z, v.z);
        ((float2*)(sA + (c4 * 4 + 3) * SA_STRIDE + wb))[0] = make_float2(v.w, v.w);
    }
    for (int i = t; i < 32 * 64; i += 256) {
        const int c = i >> 6, jj = i & 63;
        const int tkw = jj >> 2, j = jj & 3;
        const float* wp = Wreg + c * K + kblk * 128 + 2 * jj;
        sW[(j >> 1) * 1024 + (c * 16 + tkw) * 2 + (j & 1)] = pack2(wp[0], wp[1]);
    }
    const float* pb = posg + ((size_t)b * NPTS + rowblk * 128) * 3;
    for (int i = t; i < 128 * 3; i += 256) {
        const int r = i / 3, d = i - r * 3;
        const float v = pb[i];
        sP[r * 6 + 2 * d] = v; sP[r * 6 + 2 * d + 1] = v;
    }
    __syncthreads();

    if (kblk == 0 && t < 128) {
        const float x = sP[t * 6 + 0], y = sP[t * 6 + 2], z = sP[t * 6 + 4];
        const float hp = 0.5f * fmaf(z, z, fmaf(y, y, x * x));
        g_pos4[(size_t)b * NPTS + rowblk * 128 + t] = make_float4(x, y, z, hp);
    }

    ull acc[8][4];
#pragma unroll
    for (int r = 0; r < 8; ++r)
#pragma unroll
        for (int j = 0; j < 4; ++j) acc[r][j] = 0ull;

    const ulonglong2* A2 = (const ulonglong2*)sA;
    const ulonglong2* WA = (const ulonglong2*)sW;
    const ulonglong2* WB = (const ulonglong2*)(sW + 1024);

#pragma unroll 4
    for (int c = 0; c < 32; ++c) {
        const ulonglong2 a0 = A2[c * 65 + 0 * 16 + tr];
        const ulonglong2 a1 = A2[c * 65 + 1 * 16 + tr];
        const ulonglong2 a2 = A2[c * 65 + 2 * 16 + tr];
        const ulonglong2 a3 = A2[c * 65 + 3 * 16 + tr];
        const ulonglong2 w0 = WA[c * 16 + tk];
        const ulonglong2 w1 = WB[c * 16 + tk];
        fma2(acc[0][0], a0.x, w0.x); fma2(acc[0][1], a0.x, w0.y);
        fma2(acc[0][2], a0.x, w1.x); fma2(acc[0][3], a0.x, w1.y);
        fma2(acc[1][0], a0.y, w0.x); fma2(acc[1][1], a0.y, w0.y);
        fma2(acc[1][2], a0.y, w1.x); fma2(acc[1][3], a0.y, w1.y);
        fma2(acc[2][0], a1.x, w0.x); fma2(acc[2][1], a1.x, w0.y);
        fma2(acc[2][2], a1.x, w1.x); fma2(acc[2][3], a1.x, w1.y);
        fma2(acc[3][0], a1.y, w0.x); fma2(acc[3][1], a1.y, w0.y);
        fma2(acc[3][2], a1.y, w1.x); fma2(acc[3][3], a1.y, w1.y);
        fma2(acc[4][0], a2.x, w0.x); fma2(acc[4][1], a2.x, w0.y);
        fma2(acc[4][2], a2.x, w1.x); fma2(acc[4][3], a2.x, w1.y);
        fma2(acc[5][0], a2.y, w0.x); fma2(acc[5][1], a2.y, w0.y);
        fma2(acc[5][2], a2.y, w1.x); fma2(acc[5][3], a2.y, w1.y);
        fma2(acc[6][0], a3.x, w0.x); fma2(acc[6][1], a3.x, w0.y);
        fma2(acc[6][2], a3.x, w1.x); fma2(acc[6][3], a3.x, w1.y);
        fma2(acc[7][0], a3.y, w0.x); fma2(acc[7][1], a3.y, w0.y);
        fma2(acc[7][2], a3.y, w1.x); fma2(acc[7][3], a3.y, w1.y);
    }

    ull Qz[4], Qx[4], Qy[4], Qw[4];
#pragma unroll
    for (int j = 0; j < 4; ++j) { Qz[j] = 0; Qx[j] = 0; Qy[j] = 0; Qw[j] = 0; }
    const ull ONE2 = pack2(1.0f, 1.0f);
#pragma unroll
    for (int r = 0; r < 8; ++r) {
        const int rg = tr * 8 + r;
        const ull px2 = *(const ull*)(sP + rg * 6 + 0);
        const ull py2 = *(const ull*)(sP + rg * 6 + 2);
        const ull pz2 = *(const ull*)(sP + rg * 6 + 4);
#pragma unroll
        for (int j = 0; j < 4; ++j) {
            float lo, hi; unpack2(acc[r][j], lo, hi);
            const ull e2 = pack2(__expf(lo), __expf(hi));
            fma2(Qz[j], e2, ONE2);
            fma2(Qx[j], e2, px2);
            fma2(Qy[j], e2, py2);
            fma2(Qw[j], e2, pz2);
        }
    }

    __syncthreads();
    ull* sred = (ull*)sA;
#pragma unroll
    for (int j = 0; j < 4; ++j) {
        const int base = tr * 260 + (tk * 4 + j) * 4;
        sred[base + 0] = Qz[j]; sred[base + 1] = Qx[j];
        sred[base + 2] = Qy[j]; sred[base + 3] = Qw[j];
    }
    __syncthreads();
    ull s = sred[t];
#pragma unroll
    for (int i = 1; i < 16; ++i) s = add2(s, sred[i * 260 + t]);
    g_part2[((size_t)(b * 2 + kblk) * 128 + rowblk) * 256 + t] = s;
#endif
}

// ---------------------------------------------------------------------------
// Kernel 2: shared-scan KNN (frozen R13 structure). Keypoint read is
// arch-guarded to match whichever partials format kernel 1 produced.
// ---------------------------------------------------------------------------
#define QPB   2
#define NW    8
#define SLICE (NPTS / NW)
#define CCAP  192

__global__ void __launch_bounds__(256) knn_extract_kernel(
    const float* __restrict__ f, const float* __restrict__ WE,
    float* __restrict__ out)
{
    __shared__ float sWE[C * C];
    __shared__ float sLM[QPB][NW][16];
    __shared__ int   sci[QPB][CCAP];
    __shared__ float skp[QPB][3];
    __shared__ float sTm[QPB];
    __shared__ int   scnt[QPB];

    const int t = threadIdx.x;
    const int w = t >> 5, lane = t & 31;
    for (int i = t; i < C * C; i += 256) sWE[i] = WE[i];
    if (t < QPB) scnt[t] = 0;

    const int pair0 = blockIdx.x * QPB;
    const int b = pair0 >> 8;

    // ---- keypoints (deterministic butterfly reduce)
    if (w < QPB) {
        const int k = (pair0 + w) & 255;
        const int bf = b * 2 + (k >> 7);
#if TC_PATH
        const int kl = k & 127;
        const float4* gp = g_part3 + (size_t)bf * 256 * 128 + kl;
        float4 s = make_float4(0.f, 0.f, 0.f, 0.f);
#pragma unroll
        for (int j = 0; j < 8; ++j) {
            const float4 v = gp[(size_t)(lane + 32 * j) * 128];
            s.x += v.x; s.y += v.y; s.z += v.z; s.w += v.w;
        }
#pragma unroll
        for (int off = 16; off; off >>= 1) {
            s.x += __shfl_xor_sync(0xffffffffu, s.x, off);
            s.y += __shfl_xor_sync(0xffffffffu, s.y, off);
            s.z += __shfl_xor_sync(0xffffffffu, s.z, off);
            s.w += __shfl_xor_sync(0xffffffffu, s.w, off);
        }
        if (lane == 0) {
            const float inv = 1.0f / s.x;
            skp[w][0] = s.y * inv; skp[w][1] = s.z * inv; skp[w][2] = s.w * inv;
        }
#else
        const int klocal = k & 127;
        const int jj = klocal >> 1, half = klocal & 1;
        const ull* gp = g_part2 + (size_t)bf * 128 * 256 + jj * 4;
        ull sZ = 0, sX = 0, sY = 0, sU = 0;
#pragma unroll
        for (int i = 0; i < 4; ++i) {
            const ull* p = gp + (size_t)(lane + 32 * i) * 256;
            sZ = add2(sZ, p[0]); sX = add2(sX, p[1]);
            sY = add2(sY, p[2]); sU = add2(sU, p[3]);
        }
#pragma unroll
        for (int off = 16; off; off >>= 1) {
            sZ = add2(sZ, __shfl_xor_sync(0xffffffffu, sZ, off));
            sX = add2(sX, __shfl_xor_sync(0xffffffffu, sX, off));
            sY = add2(sY, __shfl_xor_sync(0xffffffffu, sY, off));
            sU = add2(sU, __shfl_xor_sync(0xffffffffu, sU, off));
        }
        if (lane == 0) {
            float Zl, Zh, xl, xh, yl, yh, ul2, uh;
            unpack2(sZ, Zl, Zh); unpack2(sX, xl, xh);
            unpack2(sY, yl, yh); unpack2(sU, ul2, uh);
            const float inv = 1.0f / (half ? Zh : Zl);
            skp[w][0] = (half ? xh : xl) * inv;
            skp[w][1] = (half ? yh : yl) * inv;
            skp[w][2] = (half ? uh : ul2) * inv;
        }
#endif
    }
    __syncthreads();

    float nkx[QPB], nky[QPB], nkz[QPB];
#pragma unroll
    for (int q = 0; q < QPB; ++q) {
        nkx[q] = -skp[q][0]; nky[q] = -skp[q][1]; nkz[q] = -skp[q][2];
    }

    const float4* pp = g_pos4 + (size_t)b * NPTS;
    const float INF = 3.4e38f;
    const int p0 = w * SLICE;

    // ---- pass 1: running min of s per query (manual x4 unroll)
    float m[QPB];
#pragma unroll
    for (int q = 0; q < QPB; ++q) m[q] = INF;
    for (int it = 0; it < SLICE / 128; ++it) {
        const int pbase = p0 + it * 128 + lane;
        const float4 v0 = pp[pbase +  0];
        const float4 v1 = pp[pbase + 32];
        const float4 v2 = pp[pbase + 64];
        const float4 v3 = pp[pbase + 96];
#pragma unroll
        for (int q = 0; q < QPB; ++q) {
            const float s0 = fmaf(v0.z, nkz[q], fmaf(v0.y, nky[q], fmaf(v0.x, nkx[q], v0.w)));
            const float s1 = fmaf(v1.z, nkz[q], fmaf(v1.y, nky[q], fmaf(v1.x, nkx[q], v1.w)));
            const float s2 = fmaf(v2.z, nkz[q], fmaf(v2.y, nky[q], fmaf(v2.x, nkx[q], v2.w)));
            const float s3 = fmaf(v3.z, nkz[q], fmaf(v3.y, nky[q], fmaf(v3.x, nkx[q], v3.w)));
            m[q] = fminf(m[q], fminf(fminf(s0, s1), fminf(s2, s3)));
        }
    }
#pragma unroll
    for (int q = 0; q < QPB; ++q) {
        float v = m[q];
#pragma unroll
        for (int kk = 2; kk <= 32; kk <<= 1) {
#pragma unroll
            for (int j = kk >> 1; j > 0; j >>= 1) {
                const float o = __shfl_xor_sync(0xffffffffu, v, j);
                const bool asc = ((lane & kk) == 0);
                const bool keepmin = (((lane & j) == 0) == asc);
                v = keepmin ? fminf(v, o) : fmaxf(v, o);
            }
        }
        if (lane < 16) sLM[q][w][lane] = v;
    }
    __syncthreads();

    if (w < QPB) {
        const int q = w;
        float md = (lane < 16) ? sLM[q][0][lane] : INF;
        float mtd = __shfl_sync(0xffffffffu, md, KNN_K - 1);
#pragma unroll
        for (int s = 1; s < NW; ++s) {
            for (int e = 0; e < 16; ++e) {
                const float dc = sLM[q][s][e];
                if (!(dc < mtd)) break;
                float pd = __shfl_up_sync(0xffffffffu, md, 1);
                if (lane == 0) pd = -INF;
                if (dc < md) md = fmaxf(pd, dc);
                mtd = __shfl_sync(0xffffffffu, md, KNN_K - 1);
            }
        }
        if (lane == 0) sTm[q] = mtd;
    }
    __syncthreads();

    float Te[QPB];
#pragma unroll
    for (int q = 0; q < QPB; ++q)
        Te[q] = sTm[q] + 4e-4f + 2e-4f * fabsf(sTm[q]);

    // ---- pass 2: compaction (manual x4 unroll, one any-ballot per 128 pts)
    const unsigned lmask = (1u << lane) - 1u;
    for (int it = 0; it < SLICE / 128; ++it) {
        const int p = p0 + it * 128 + lane;
        const float4 v0 = pp[p +  0];
        const float4 v1 = pp[p + 32];
        const float4 v2 = pp[p + 64];
        const float4 v3 = pp[p + 96];
        float s0[QPB], s1[QPB], s2[QPB], s3[QPB];
        bool f0[QPB], f1[QPB], f2[QPB], f3[QPB];
        bool any = false;
#pragma unroll
        for (int q = 0; q < QPB; ++q) {
            s0[q] = fmaf(v0.z, nkz[q], fmaf(v0.y, nky[q], fmaf(v0.x, nkx[q], v0.w)));
            s1[q] = fmaf(v1.z, nkz[q], fmaf(v1.y, nky[q], fmaf(v1.x, nkx[q], v1.w)));
            s2[q] = fmaf(v2.z, nkz[q], fmaf(v2.y, nky[q], fmaf(v2.x, nkx[q], v2.w)));
            s3[q] = fmaf(v3.z, nkz[q], fmaf(v3.y, nky[q], fmaf(v3.x, nkx[q], v3.w)));
            f0[q] = (s0[q] <= Te[q]); f1[q] = (s1[q] <= Te[q]);
            f2[q] = (s2[q] <= Te[q]); f3[q] = (s3[q] <= Te[q]);
            any |= (f0[q] | f1[q] | f2[q] | f3[q]);
        }
        if (__ballot_sync(0xffffffffu, any) == 0u) continue;
#pragma unroll
        for (int q = 0; q < QPB; ++q) {
            const bool fs[4] = {f0[q], f1[q], f2[q], f3[q]};
#pragma unroll
            for (int jc = 0; jc < 4; ++jc) {
                const unsigned mm = __ballot_sync(0xffffffffu, fs[jc]);
                if (mm) {
                    const int leader = __ffs(mm) - 1;
                    int base = 0;
                    if (lane == leader) base = atomicAdd(&scnt[q], __popc(mm));
                    base = __shfl_sync(0xffffffffu, base, leader);
                    if (fs[jc]) {
                        const int o = base + __popc(mm & lmask);
                        if (o < CCAP) sci[q][o] = p + jc * 32;
                    }
                }
            }
        }
    }
    __syncthreads();

    // ---- pass 3: exact lex (d2, idx) selection + gather + GEMV
    if (w < QPB) {
        const int q = w;
        const int pair = pair0 + q;
        const float kx = skp[q][0], ky = skp[q][1], kz = skp[q][2];
        int cnt = scnt[q]; if (cnt > CCAP) cnt = CCAP;

        float md = INF; int mi = 0x7fffffff;
        if (lane < cnt) {
            mi = sci[q][lane];
            const float4 v = pp[mi];
            const float dx = v.x - kx, dy = v.y - ky, dz = v.z - kz;
            md = fmaf(dx, dx, fmaf(dy, dy, dz * dz));
        }
#pragma unroll
        for (int kk = 2; kk <= 32; kk <<= 1) {
#pragma unroll
            for (int j = kk >> 1; j > 0; j >>= 1) {
                const float od = __shfl_xor_sync(0xffffffffu, md, j);
                const int   oi = __shfl_xor_sync(0xffffffffu, mi, j);
                const bool asc = ((lane & kk) == 0);
                const bool low = ((lane & j) == 0);
                const bool oLess = (od < md) || (od == md && oi < mi);
                const bool takeOther = (low == asc) ? oLess : !oLess;
                if (takeOther) { md = od; mi = oi; }
            }
        }
        float mtd = __shfl_sync(0xffffffffu, md, KNN_K - 1);
        int   mti = __shfl_sync(0xffffffffu, mi, KNN_K - 1);

        for (int base0 = 32; base0 < cnt; base0 += 32) {
            const int jjx = base0 + lane;
            float cd2 = INF; int ci2 = 0x7fffffff;
            if (jjx < cnt) {
                ci2 = sci[q][jjx];
                const float4 v = pp[ci2];
                const float dx = v.x - kx, dy = v.y - ky, dz = v.z - kz;
                cd2 = fmaf(dx, dx, fmaf(dy, dy, dz * dz));
            }
#pragma unroll
            for (int kk = 2; kk <= 32; kk <<= 1) {
#pragma unroll
                for (int j = kk >> 1; j > 0; j >>= 1) {
                    const float od = __shfl_xor_sync(0xffffffffu, cd2, j);
                    const int   oi = __shfl_xor_sync(0xffffffffu, ci2, j);
                    const bool asc = ((lane & kk) == 0);
                    const bool low = ((lane & j) == 0);
                    const bool oLess = (od < cd2) || (od == cd2 && oi < ci2);
                    const bool takeOther = (low == asc) ? oLess : !oLess;
                    if (takeOther) { cd2 = od; ci2 = oi; }
                }
            }
            for (int e = 0; e < 32; ++e) {
                const float dc = __shfl_sync(0xffffffffu, cd2, e);
                const int   ic = __shfl_sync(0xffffffffu, ci2, e);
                if (!(dc < mtd || (dc == mtd && ic < mti))) break;
                float pd = __shfl_up_sync(0xffffffffu, md, 1);
                int   pi = __shfl_up_sync(0xffffffffu, mi, 1);
                if (lane == 0) { pd = -INF; pi = -1; }
                const bool disp = (dc < md) || (dc == md && ic < mi);
                if (disp) {
                    const bool tp = (pd > dc) || (pd == dc && pi > ic);
                    md = tp ? pd : dc;
                    mi = tp ? pi : ic;
                }
                mtd = __shfl_sync(0xffffffffu, md, KNN_K - 1);
                mti = __shfl_sync(0xffffffffu, mi, KNN_K - 1);
            }
        }

        const float* fbase = f + (size_t)b * NPTS * C;
        float acc = 0.f;
#pragma unroll
        for (int r = 0; r < KNN_K; ++r) {
            const int id = __shfl_sync(0xffffffffu, mi, r);
            acc += fbase[(size_t)id * C + lane];
        }
        acc *= (1.0f / KNN_K);

        float o = 0.f;
#pragma unroll
        for (int c = 0; c < C; ++c)
            o = fmaf(__shfl_sync(0xffffffffu, acc, c), sWE[c * C + lane], o);

        out[(size_t)pair * C + lane] = o;
    }
}

// ---------------------------------------------------------------------------
// Inputs: feature, pos, W_pool (dead code), W_regress, W_extract, bs.
// ---------------------------------------------------------------------------
extern "C" void kernel_launch(void* const* d_in, const int* in_sizes, int n_in,
                              void* d_out, int out_size)
{
    (void)in_sizes; (void)n_in; (void)out_size;
    const float* f    = (const float*)d_in[0];
    const float* pos  = (const float*)d_in[1];
    const float* Wreg = (const float*)d_in[3];
    const float* WE   = (const float*)d_in[4];
    float* out = (float*)d_out;

    static int attr_set = 0;
    if (!attr_set) {
        cudaFuncSetAttribute(regress_kernel,
                             cudaFuncAttributeMaxDynamicSharedMemorySize, SMEM_DYN);
        attr_set = 1;
    }
    dim3 g1(NPTS / 128, 2, BS);
    regress_kernel<<<g1, 256, SMEM_DYN>>>(f, pos, Wreg);
    knn_extract_kernel<<<BS * K / QPB, 256>>>(f, WE, out);
}

// round 17
// speedup vs baseline: 2.1037x; 1.2589x over previous
#include <cuda_runtime.h>
#include <cuda_bf16.h>

#define BS     8
#define NPTS   16384
#define C      32
#define K      256
#define KNN_K  16

typedef unsigned long long ull;

// Arch-specific dispatch: tcgen05 only exists in the sm_103a cubin; the
// compute_103 PTX stage (and any JIT fallback) gets the proven FFMA2 path.
// Only CODE may be guarded — no __device__ objects inside the guard (R15).
#if defined(__CUDA_ARCH_FEAT_SM103_ALL)
#define TC_PATH 1
#else
#define TC_PATH 0
#endif

// -------------------- f32x2 packed helpers --------------------
__device__ __forceinline__ ull pack2(float a, float b) {
    ull r; asm("mov.b64 %0, {%1,%2};" : "=l"(r) : "f"(a), "f"(b)); return r;
}
__device__ __forceinline__ void unpack2(ull v, float& lo, float& hi) {
    asm("mov.b64 {%0,%1}, %2;" : "=f"(lo), "=f"(hi) : "l"(v));
}
__device__ __forceinline__ void fma2(ull& d, ull a, ull b) {
    asm("fma.rn.f32x2 %0, %1, %2, %0;" : "+l"(d) : "l"(a), "l"(b));
}
__device__ __forceinline__ ull add2(ull a, ull b) {
    ull r; asm("add.rn.f32x2 %0, %1, %2;" : "=l"(r) : "l"(a), "l"(b)); return r;
}
__device__ __forceinline__ unsigned smem_u32(const void* p) {
    unsigned a;
    asm("{ .reg .u64 t; cvta.to.shared.u64 t, %1; cvt.u32.u64 %0, t; }"
        : "=r"(a) : "l"(p));
    return a;
}
#define SW128(off) ((off) ^ (((off) >> 3) & 0x70))
#define SMEM_DESC_BASE_ULL ((2ull << 61) | (1ull << 46) | (64ull << 32) | (1ull << 16))

// -------------------- scratch (static device arrays, unconditional) -------
__device__ ull    g_part2[16 * 128 * 256];   // fallback partials
__device__ float4 g_part3[16 * 256 * 128];   // tcgen05 partials
__device__ float4 g_pos4[BS * NPTS];         // (x, y, z, 0.5*|p|^2)

// ---------------------------------------------------------------------------
// tcgen05-only PTX wrappers (compiled only in the sm_103a cubin)
// ---------------------------------------------------------------------------
#if TC_PATH
__device__ __forceinline__ unsigned elect_one() {
    unsigned p;
    asm volatile("{ .reg .pred p; elect.sync _|p, 0xFFFFFFFF; selp.b32 %0, 1, 0, p; }"
                 : "=r"(p));
    return p;
}
__device__ __forceinline__ ull make_desc(unsigned smem_addr) {
    return SMEM_DESC_BASE_ULL | ((ull)(smem_addr >> 4) & 0x3FFF);
}
__device__ __forceinline__ void mma_f16_ss_cg1(
    unsigned d_tmem, ull a_desc, ull b_desc, unsigned idesc, unsigned en)
{
    asm volatile(
        "{\n\t.reg .pred p;\n\tsetp.ne.u32 p, %5, 0;\n\t"
        "tcgen05.mma.cta_group::1.kind::f16 [%0], %1, %2, %3, {%4,%4,%4,%4}, p;\n\t}"
        :: "r"(d_tmem), "l"(a_desc), "l"(b_desc), "r"(idesc), "r"(0u), "r"(en)
        : "memory");
}
#define TC_ALLOC(sm, n)  asm volatile("tcgen05.alloc.cta_group::1.sync.aligned.shared::cta.b32 [%0], %1;" :: "r"(sm), "r"(n) : "memory")
#define TC_DEALLOC(tm,n) asm volatile("tcgen05.dealloc.cta_group::1.sync.aligned.b32 %0, %1;" :: "r"(tm), "r"(n))
#define TC_RELINQ()      asm volatile("tcgen05.relinquish_alloc_permit.cta_group::1.sync.aligned;")
#define TC_COMMIT(mb)    asm volatile("tcgen05.commit.cta_group::1.mbarrier::arrive::one.shared::cluster.b64 [%0];" :: "r"(mb) : "memory")
#define TC_FENCE_AFTER() asm volatile("tcgen05.fence::after_thread_sync;" ::: "memory")
#define TC_WAIT_LD()     asm volatile("tcgen05.wait::ld.sync.aligned;" ::: "memory")
#define FENCE_ASYNC()    asm volatile("fence.proxy.async.shared::cta;" ::: "memory")
#define MBAR_INIT(mb,c)  asm volatile("mbarrier.init.shared.b64 [%0], %1;" :: "r"(mb), "r"(c) : "memory")
#define MBAR_INVAL(mb)   asm volatile("mbarrier.inval.shared.b64 [%0];" :: "r"(mb) : "memory")
#define MBAR_WAIT(mb, ph) do { \
    unsigned _mb = (mb), _ph = (ph), _done; \
    asm volatile("{\n\t.reg .pred p;\n\tmbarrier.try_wait.parity.acquire.cta.shared::cta.b64 p, [%1], %2;\n\tselp.b32 %0, 1, 0, p;\n\t}" \
        : "=r"(_done) : "r"(_mb), "r"(_ph) : "memory"); \
    if (!_done) { \
        asm volatile("{\n\t.reg .pred P1;\n\tWL_%=:\n\tmbarrier.try_wait.parity.acquire.cta.shared::cta.b64 P1, [%0], %1, 0x989680;\n\t@P1 bra.uni WD_%=;\n\tbra.uni WL_%=;\n\tWD_%=:\n\t}" \
            :: "r"(_mb), "r"(_ph) : "memory"); \
    } \
} while (0)
#define LDTM_X16(r, a) \
    asm volatile("tcgen05.ld.sync.aligned.32x32b.x16.b32 " \
        "{%0,%1,%2,%3,%4,%5,%6,%7,%8,%9,%10,%11,%12,%13,%14,%15}, [%16];" \
        : "=r"((r)[0]),"=r"((r)[1]),"=r"((r)[2]),"=r"((r)[3]), \
          "=r"((r)[4]),"=r"((r)[5]),"=r"((r)[6]),"=r"((r)[7]), \
          "=r"((r)[8]),"=r"((r)[9]),"=r"((r)[10]),"=r"((r)[11]), \
          "=r"((r)[12]),"=r"((r)[13]),"=r"((r)[14]),"=r"((r)[15]) \
        : "r"(a))
#endif

// tcgen05-path smem layout (dynamic)
#define TILE_A   0
#define TILE_B   16384
#define TILE_3   32768
#define OFF_POS  49152
#define OFF_TPTR 51200
#define OFF_MBAR 51208
#define SMEM_DYN 51264
#define MMA_IDESC 0x8200490u   // F32 acc, bf16 x bf16, M=128, N=128

#define SA_STRIDE 260

// ---------------------------------------------------------------------------
// Kernel 1: s[b,n,k] = f[b,n,:]·Wreg[0:32,k] (pooling head cancels in the
// softmax over n) + exp epilogue -> partial (Z, wx, wy, wz).
// TC_PATH: bf16 triple-split SS tcgen05 MMA, paired bf16x2 staging stores,
// LDTM x16 chunks (regs < 64 -> 4 blocks/SM; TMEM 4x128 = 512 cols exact).
// else: the proven R13 FFMA2 register-tiled GEMM.
// ---------------------------------------------------------------------------
__global__ void __launch_bounds__(256, TC_PATH ? 4 : 2) regress_kernel(
    const float* __restrict__ f, const float* __restrict__ posg,
    const float* __restrict__ Wreg)
{
#if TC_PATH
    extern __shared__ char smem[];
    const unsigned sbase = smem_u32(smem);
    const int rowblk = blockIdx.x, kblk = blockIdx.y, b = blockIdx.z;
    const int t = threadIdx.x;
    const int w = t >> 5, lane = t & 31;

    if (w == 0) { TC_ALLOC(sbase + OFF_TPTR, 128); TC_RELINQ(); }
    if (t == 0) MBAR_INIT(sbase + OFF_MBAR, 1);

    // ---- stage B = F tile [n=128 rows, c=32], bf16 triple split, paired
    {
        const float2* fb2 = (const float2*)(f + ((size_t)b * NPTS + rowblk * 128) * C);
#pragma unroll
        for (int i = 0; i < 8; ++i) {
            const int idx = t + i * 256;          // pair idx: row*16 + cp
            const int row = idx >> 4, cp = idx & 15;
            const float2 v = fb2[idx];
            const __nv_bfloat16 h1x = __float2bfloat16_rn(v.x);
            const __nv_bfloat16 h1y = __float2bfloat16_rn(v.y);
            const float r1x = v.x - __bfloat162float(h1x);
            const float r1y = v.y - __bfloat162float(h1y);
            const __nv_bfloat16 h2x = __float2bfloat16_rn(r1x);
            const __nv_bfloat16 h2y = __float2bfloat16_rn(r1y);
            const float r2x = r1x - __bfloat162float(h2x);
            const float r2y = r1y - __bfloat162float(h2y);
            __nv_bfloat162 H1; H1.x = h1x; H1.y = h1y;
            __nv_bfloat162 H2; H2.x = h2x; H2.y = h2y;
            __nv_bfloat162 H3; H3.x = __float2bfloat16_rn(r2x);
                              H3.y = __float2bfloat16_rn(r2y);
            const int base = row * 128 + cp * 4;  // 4B-aligned, SW128-safe
            *(__nv_bfloat162*)(smem + TILE_B + SW128(base))      = H1;
            *(__nv_bfloat162*)(smem + TILE_B + SW128(base + 64)) = H2;
            *(__nv_bfloat162*)(smem + TILE_3 + SW128(base + 64)) = H3;
        }
    }
    // ---- stage A = W^T tile [k=128 rows, c=32], bf16 triple split, paired
    {
#pragma unroll
        for (int i = 0; i < 8; ++i) {
            const int idx = t + i * 256;
            const int row = idx >> 4, cp = idx & 15;     // row = k local
            const float vx = Wreg[(2 * cp)     * K + kblk * 128 + row];
            const float vy = Wreg[(2 * cp + 1) * K + kblk * 128 + row];
            const __nv_bfloat16 h1x = __float2bfloat16_rn(vx);
            const __nv_bfloat16 h1y = __float2bfloat16_rn(vy);
            const float r1x = vx - __bfloat162float(h1x);
            const float r1y = vy - __bfloat162float(h1y);
            const __nv_bfloat16 h2x = __float2bfloat16_rn(r1x);
            const __nv_bfloat16 h2y = __float2bfloat16_rn(r1y);
            const float r2x = r1x - __bfloat162float(h2x);
            const float r2y = r1y - __bfloat162float(h2y);
            __nv_bfloat162 H1; H1.x = h1x; H1.y = h1y;
            __nv_bfloat162 H2; H2.x = h2x; H2.y = h2y;
            __nv_bfloat162 H3; H3.x = __float2bfloat16_rn(r2x);
                              H3.y = __float2bfloat16_rn(r2y);
            const int base = row * 128 + cp * 4;
            *(__nv_bfloat162*)(smem + TILE_A + SW128(base))      = H1;
            *(__nv_bfloat162*)(smem + TILE_A + SW128(base + 64)) = H2;
            *(__nv_bfloat162*)(smem + TILE_3 + SW128(base))      = H3;
        }
    }
    // ---- stage positions block-locally (race-free); publish g_pos4 once
    if (t < 128) {
        const float* pr = posg + ((size_t)b * NPTS + rowblk * 128 + t) * 3;
        const float x = pr[0], y = pr[1], z = pr[2];
        const float hp = 0.5f * fmaf(z, z, fmaf(y, y, x * x));
        ((float4*)(smem + OFF_POS))[t] = make_float4(x, y, z, hp);
        if (kblk == 0)
            g_pos4[(size_t)b * NPTS + rowblk * 128 + t] = make_float4(x, y, z, hp);
    }
    FENCE_ASYNC();
    __syncthreads();

    unsigned tmem;
    asm volatile("ld.shared.b32 %0, [%1];" : "=r"(tmem) : "r"(sbase + OFF_TPTR));

    if (w == 0 && elect_one()) {
        const ull dA = make_desc(sbase + TILE_A);
        const ull dB = make_desc(sbase + TILE_B);
        const ull d3 = make_desc(sbase + TILE_3);
        mma_f16_ss_cg1(tmem, dA + 0, dB + 0, MMA_IDESC, 0);  // a1b1
        mma_f16_ss_cg1(tmem, dA + 2, dB + 2, MMA_IDESC, 1);
        mma_f16_ss_cg1(tmem, dA + 0, dB + 4, MMA_IDESC, 1);  // a1b2
        mma_f16_ss_cg1(tmem, dA + 2, dB + 6, MMA_IDESC, 1);
        mma_f16_ss_cg1(tmem, dA + 4, dB + 0, MMA_IDESC, 1);  // a2b1
        mma_f16_ss_cg1(tmem, dA + 6, dB + 2, MMA_IDESC, 1);
        mma_f16_ss_cg1(tmem, dA + 0, d3 + 4, MMA_IDESC, 1);  // a1b3
        mma_f16_ss_cg1(tmem, dA + 2, d3 + 6, MMA_IDESC, 1);
        mma_f16_ss_cg1(tmem, dA + 4, dB + 4, MMA_IDESC, 1);  // a2b2
        mma_f16_ss_cg1(tmem, dA + 6, dB + 6, MMA_IDESC, 1);
        mma_f16_ss_cg1(tmem, d3 + 0, dB + 0, MMA_IDESC, 1);  // a3b1
        mma_f16_ss_cg1(tmem, d3 + 2, dB + 2, MMA_IDESC, 1);
        TC_COMMIT(sbase + OFF_MBAR);
    }
    __syncthreads();
    MBAR_WAIT(sbase + OFF_MBAR, 0);
    TC_FENCE_AFTER();

    // ---- epilogue: warp w reads its subpartition (lanes = k), cols = n,
    //      in x16 chunks to keep register count < 64 (occupancy 4)
    const int half = w >> 2;
    const int nbase = half * 64;
    const float4* pp = (const float4*)(smem + OFF_POS) + nbase;
    float Qz = 0.f, Qx = 0.f, Qy = 0.f, Qw = 0.f;
#pragma unroll
    for (int ch = 0; ch < 4; ++ch) {
        unsigned dr[16];
        LDTM_X16(dr, tmem + nbase + ch * 16);
        TC_WAIT_LD();
#pragma unroll
        for (int j = 0; j < 16; ++j) {
            const float4 p = pp[ch * 16 + j];   // smem uniform broadcast
            const float e = __expf(__uint_as_float(dr[j]));
            Qz += e;
            Qx = fmaf(e, p.x, Qx);
            Qy = fmaf(e, p.y, Qy);
            Qw = fmaf(e, p.z, Qw);
        }
    }
    {
        const int bf = b * 2 + kblk;
        const int klane = (w & 3) * 32 + lane;
        g_part3[((size_t)(bf * 128 + rowblk) * 2 + half) * 128 + klane] =
            make_float4(Qz, Qx, Qy, Qw);
    }
    __syncthreads();
    if (t == 0) MBAR_INVAL(sbase + OFF_MBAR);
    __syncthreads();
    if (w == 0) TC_DEALLOC(tmem, 128);

#else  // ---------------- fallback: R13 FFMA2 path (proven) ----------------
    const int rowblk = blockIdx.x, kblk = blockIdx.y, b = blockIdx.z;
    const int t = threadIdx.x;
    const int tk = t & 15, tr = t >> 4;

    __shared__ float sA[32 * SA_STRIDE];
    __shared__ ull   sW[32 * 64];
    __shared__ float sP[128 * 6];

    const float4* f4 = (const float4*)(f + ((size_t)b * NPTS + rowblk * 128) * C);
#pragma unroll
    for (int i = 0; i < 4; ++i) {
        const int idx = t + i * 256;
        const int r = idx >> 3, c4 = idx & 7;
        const float4 v = f4[idx];
        const int wb = ((r & 7) >> 1) * 64 + (r >> 3) * 4 + (r & 1) * 2;
        ((float2*)(sA + (c4 * 4 + 0) * SA_STRIDE + wb))[0] = make_float2(v.x, v.x);
        ((float2*)(sA + (c4 * 4 + 1) * SA_STRIDE + wb))[0] = make_float2(v.y, v.y);
        ((float2*)(sA + (c4 * 4 + 2) * SA_STRIDE + wb))[0] = make_float2(v.z, v.z);
        ((float2*)(sA + (c4 * 4 + 3) * SA_STRIDE + wb))[0] = make_float2(v.w, v.w);
    }
    for (int i = t; i < 32 * 64; i += 256) {
        const int c = i >> 6, jj = i & 63;
        const int tkw = jj >> 2, j = jj & 3;
        const float* wp = Wreg + c * K + kblk * 128 + 2 * jj;
        sW[(j >> 1) * 1024 + (c * 16 + tkw) * 2 + (j & 1)] = pack2(wp[0], wp[1]);
    }
    const float* pb = posg + ((size_t)b * NPTS + rowblk * 128) * 3;
    for (int i = t; i < 128 * 3; i += 256) {
        const int r = i / 3, d = i - r * 3;
        const float v = pb[i];
        sP[r * 6 + 2 * d] = v; sP[r * 6 + 2 * d + 1] = v;
    }
    __syncthreads();

    if (kblk == 0 && t < 128) {
        const float x = sP[t * 6 + 0], y = sP[t * 6 + 2], z = sP[t * 6 + 4];
        const float hp = 0.5f * fmaf(z, z, fmaf(y, y, x * x));
        g_pos4[(size_t)b * NPTS + rowblk * 128 + t] = make_float4(x, y, z, hp);
    }

    ull acc[8][4];
#pragma unroll
    for (int r = 0; r < 8; ++r)
#pragma unroll
        for (int j = 0; j < 4; ++j) acc[r][j] = 0ull;

    const ulonglong2* A2 = (const ulonglong2*)sA;
    const ulonglong2* WA = (const ulonglong2*)sW;
    const ulonglong2* WB = (const ulonglong2*)(sW + 1024);

#pragma unroll 4
    for (int c = 0; c < 32; ++c) {
        const ulonglong2 a0 = A2[c * 65 + 0 * 16 + tr];
        const ulonglong2 a1 = A2[c * 65 + 1 * 16 + tr];
        const ulonglong2 a2 = A2[c * 65 + 2 * 16 + tr];
        const ulonglong2 a3 = A2[c * 65 + 3 * 16 + tr];
        const ulonglong2 w0 = WA[c * 16 + tk];
        const ulonglong2 w1 = WB[c * 16 + tk];
        fma2(acc[0][0], a0.x, w0.x); fma2(acc[0][1], a0.x, w0.y);
        fma2(acc[0][2], a0.x, w1.x); fma2(acc[0][3], a0.x, w1.y);
        fma2(acc[1][0], a0.y, w0.x); fma2(acc[1][1], a0.y, w0.y);
        fma2(acc[1][2], a0.y, w1.x); fma2(acc[1][3], a0.y, w1.y);
        fma2(acc[2][0], a1.x, w0.x); fma2(acc[2][1], a1.x, w0.y);
        fma2(acc[2][2], a1.x, w1.x); fma2(acc[2][3], a1.x, w1.y);
        fma2(acc[3][0], a1.y, w0.x); fma2(acc[3][1], a1.y, w0.y);
        fma2(acc[3][2], a1.y, w1.x); fma2(acc[3][3], a1.y, w1.y);
        fma2(acc[4][0], a2.x, w0.x); fma2(acc[4][1], a2.x, w0.y);
        fma2(acc[4][2], a2.x, w1.x); fma2(acc[4][3], a2.x, w1.y);
        fma2(acc[5][0], a2.y, w0.x); fma2(acc[5][1], a2.y, w0.y);
        fma2(acc[5][2], a2.y, w1.x); fma2(acc[5][3], a2.y, w1.y);
        fma2(acc[6][0], a3.x, w0.x); fma2(acc[6][1], a3.x, w0.y);
        fma2(acc[6][2], a3.x, w1.x); fma2(acc[6][3], a3.x, w1.y);
        fma2(acc[7][0], a3.y, w0.x); fma2(acc[7][1], a3.y, w0.y);
        fma2(acc[7][2], a3.y, w1.x); fma2(acc[7][3], a3.y, w1.y);
    }

    ull Qz[4], Qx[4], Qy[4], Qw[4];
#pragma unroll
    for (int j = 0; j < 4; ++j) { Qz[j] = 0; Qx[j] = 0; Qy[j] = 0; Qw[j] = 0; }
    const ull ONE2 = pack2(1.0f, 1.0f);
#pragma unroll
    for (int r = 0; r < 8; ++r) {
        const int rg = tr * 8 + r;
        const ull px2 = *(const ull*)(sP + rg * 6 + 0);
        const ull py2 = *(const ull*)(sP + rg * 6 + 2);
        const ull pz2 = *(const ull*)(sP + rg * 6 + 4);
#pragma unroll
        for (int j = 0; j < 4; ++j) {
            float lo, hi; unpack2(acc[r][j], lo, hi);
            const ull e2 = pack2(__expf(lo), __expf(hi));
            fma2(Qz[j], e2, ONE2);
            fma2(Qx[j], e2, px2);
            fma2(Qy[j], e2, py2);
            fma2(Qw[j], e2, pz2);
        }
    }

    __syncthreads();
    ull* sred = (ull*)sA;
#pragma unroll
    for (int j = 0; j < 4; ++j) {
        const int base = tr * 260 + (tk * 4 + j) * 4;
        sred[base + 0] = Qz[j]; sred[base + 1] = Qx[j];
        sred[base + 2] = Qy[j]; sred[base + 3] = Qw[j];
    }
    __syncthreads();
    ull s = sred[t];
#pragma unroll
    for (int i = 1; i < 16; ++i) s = add2(s, sred[i * 260 + t]);
    g_part2[((size_t)(b * 2 + kblk) * 128 + rowblk) * 256 + t] = s;
#endif
}

// ---------------------------------------------------------------------------
// Kernel 2: shared-scan KNN. QPB=4 queries share every loaded point (pos4
// traffic per query halved vs R16); 8 scan-warps, 512 blocks.
// ---------------------------------------------------------------------------
#define QPB   4
#define NW    8
#define SLICE (NPTS / NW)
#define CCAP  192

__global__ void __launch_bounds__(256) knn_extract_kernel(
    const float* __restrict__ f, const float* __restrict__ WE,
    float* __restrict__ out)
{
    __shared__ float sWE[C * C];
    __shared__ float sLM[QPB][NW][16];
    __shared__ int   sci[QPB][CCAP];
    __shared__ float skp[QPB][3];
    __shared__ float sTm[QPB];
    __shared__ int   scnt[QPB];

    const int t = threadIdx.x;
    const int w = t >> 5, lane = t & 31;
    for (int i = t; i < C * C; i += 256) sWE[i] = WE[i];
    if (t < QPB) scnt[t] = 0;

    const int pair0 = blockIdx.x * QPB;
    const int b = pair0 >> 8;

    // ---- keypoints (deterministic butterfly reduce), warps 0..QPB-1
    if (w < QPB) {
        const int k = (pair0 + w) & 255;
        const int bf = b * 2 + (k >> 7);
#if TC_PATH
        const int kl = k & 127;
        const float4* gp = g_part3 + (size_t)bf * 256 * 128 + kl;
        float4 s = make_float4(0.f, 0.f, 0.f, 0.f);
#pragma unroll
        for (int j = 0; j < 8; ++j) {
            const float4 v = gp[(size_t)(lane + 32 * j) * 128];
            s.x += v.x; s.y += v.y; s.z += v.z; s.w += v.w;
        }
#pragma unroll
        for (int off = 16; off; off >>= 1) {
            s.x += __shfl_xor_sync(0xffffffffu, s.x, off);
            s.y += __shfl_xor_sync(0xffffffffu, s.y, off);
            s.z += __shfl_xor_sync(0xffffffffu, s.z, off);
            s.w += __shfl_xor_sync(0xffffffffu, s.w, off);
        }
        if (lane == 0) {
            const float inv = 1.0f / s.x;
            skp[w][0] = s.y * inv; skp[w][1] = s.z * inv; skp[w][2] = s.w * inv;
        }
#else
        const int klocal = k & 127;
        const int jj = klocal >> 1, half = klocal & 1;
        const ull* gp = g_part2 + (size_t)bf * 128 * 256 + jj * 4;
        ull sZ = 0, sX = 0, sY = 0, sU = 0;
#pragma unroll
        for (int i = 0; i < 4; ++i) {
            const ull* p = gp + (size_t)(lane + 32 * i) * 256;
            sZ = add2(sZ, p[0]); sX = add2(sX, p[1]);
            sY = add2(sY, p[2]); sU = add2(sU, p[3]);
        }
#pragma unroll
        for (int off = 16; off; off >>= 1) {
            sZ = add2(sZ, __shfl_xor_sync(0xffffffffu, sZ, off));
            sX = add2(sX, __shfl_xor_sync(0xffffffffu, sX, off));
            sY = add2(sY, __shfl_xor_sync(0xffffffffu, sY, off));
            sU = add2(sU, __shfl_xor_sync(0xffffffffu, sU, off));
        }
        if (lane == 0) {
            float Zl, Zh, xl, xh, yl, yh, ul2, uh;
            unpack2(sZ, Zl, Zh); unpack2(sX, xl, xh);
            unpack2(sY, yl, yh); unpack2(sU, ul2, uh);
            const float inv = 1.0f / (half ? Zh : Zl);
            skp[w][0] = (half ? xh : xl) * inv;
            skp[w][1] = (half ? yh : yl) * inv;
            skp[w][2] = (half ? uh : ul2) * inv;
        }
#endif
    }
    __syncthreads();

    float nkx[QPB], nky[QPB], nkz[QPB];
#pragma unroll
    for (int q = 0; q < QPB; ++q) {
        nkx[q] = -skp[q][0]; nky[q] = -skp[q][1]; nkz[q] = -skp[q][2];
    }

    const float4* pp = g_pos4 + (size_t)b * NPTS;
    const float INF = 3.4e38f;
    const int p0 = w * SLICE;

    // ---- pass 1: running min of s per query (manual x4 unroll)
    float m[QPB];
#pragma unroll
    for (int q = 0; q < QPB; ++q) m[q] = INF;
    for (int it = 0; it < SLICE / 128; ++it) {
        const int pbase = p0 + it * 128 + lane;
        const float4 v0 = pp[pbase +  0];
        const float4 v1 = pp[pbase + 32];
        const float4 v2 = pp[pbase + 64];
        const float4 v3 = pp[pbase + 96];
#pragma unroll
        for (int q = 0; q < QPB; ++q) {
            const float s0 = fmaf(v0.z, nkz[q], fmaf(v0.y, nky[q], fmaf(v0.x, nkx[q], v0.w)));
            const float s1 = fmaf(v1.z, nkz[q], fmaf(v1.y, nky[q], fmaf(v1.x, nkx[q], v1.w)));
            const float s2 = fmaf(v2.z, nkz[q], fmaf(v2.y, nky[q], fmaf(v2.x, nkx[q], v2.w)));
            const float s3 = fmaf(v3.z, nkz[q], fmaf(v3.y, nky[q], fmaf(v3.x, nkx[q], v3.w)));
            m[q] = fminf(m[q], fminf(fminf(s0, s1), fminf(s2, s3)));
        }
    }
#pragma unroll
    for (int q = 0; q < QPB; ++q) {
        float v = m[q];
#pragma unroll
        for (int kk = 2; kk <= 32; kk <<= 1) {
#pragma unroll
            for (int j = kk >> 1; j > 0; j >>= 1) {
                const float o = __shfl_xor_sync(0xffffffffu, v, j);
                const bool asc = ((lane & kk) == 0);
                const bool keepmin = (((lane & j) == 0) == asc);
                v = keepmin ? fminf(v, o) : fmaxf(v, o);
            }
        }
        if (lane < 16) sLM[q][w][lane] = v;
    }
    __syncthreads();

    if (w < QPB) {
        const int q = w;
        float md = (lane < 16) ? sLM[q][0][lane] : INF;
        float mtd = __shfl_sync(0xffffffffu, md, KNN_K - 1);
#pragma unroll
        for (int s = 1; s < NW; ++s) {
            for (int e = 0; e < 16; ++e) {
                const float dc = sLM[q][s][e];
                if (!(dc < mtd)) break;
                float pd = __shfl_up_sync(0xffffffffu, md, 1);
                if (lane == 0) pd = -INF;
                if (dc < md) md = fmaxf(pd, dc);
                mtd = __shfl_sync(0xffffffffu, md, KNN_K - 1);
            }
        }
        if (lane == 0) sTm[q] = mtd;
    }
    __syncthreads();

    float Te[QPB];
#pragma unroll
    for (int q = 0; q < QPB; ++q)
        Te[q] = sTm[q] + 4e-4f + 2e-4f * fabsf(sTm[q]);

    // ---- pass 2: compaction (manual x4 unroll, one any-ballot per 128 pts)
    const unsigned lmask = (1u << lane) - 1u;
    for (int it = 0; it < SLICE / 128; ++it) {
        const int p = p0 + it * 128 + lane;
        const float4 v0 = pp[p +  0];
        const float4 v1 = pp[p + 32];
        const float4 v2 = pp[p + 64];
        const float4 v3 = pp[p + 96];
        float s0[QPB], s1[QPB], s2[QPB], s3[QPB];
        bool f0[QPB], f1[QPB], f2[QPB], f3[QPB];
        bool any = false;
#pragma unroll
        for (int q = 0; q < QPB; ++q) {
            s0[q] = fmaf(v0.z, nkz[q], fmaf(v0.y, nky[q], fmaf(v0.x, nkx[q], v0.w)));
            s1[q] = fmaf(v1.z, nkz[q], fmaf(v1.y, nky[q], fmaf(v1.x, nkx[q], v1.w)));
            s2[q] = fmaf(v2.z, nkz[q], fmaf(v2.y, nky[q], fmaf(v2.x, nkx[q], v2.w)));
            s3[q] = fmaf(v3.z, nkz[q], fmaf(v3.y, nky[q], fmaf(v3.x, nkx[q], v3.w)));
            f0[q] = (s0[q] <= Te[q]); f1[q] = (s1[q] <= Te[q]);
            f2[q] = (s2[q] <= Te[q]); f3[q] = (s3[q] <= Te[q]);
            any |= (f0[q] | f1[q] | f2[q] | f3[q]);
        }
        if (__ballot_sync(0xffffffffu, any) == 0u) continue;
#pragma unroll
        for (int q = 0; q < QPB; ++q) {
            const bool fs[4] = {f0[q], f1[q], f2[q], f3[q]};
#pragma unroll
            for (int jc = 0; jc < 4; ++jc) {
                const unsigned mm = __ballot_sync(0xffffffffu, fs[jc]);
                if (mm) {
                    const int leader = __ffs(mm) - 1;
                    int base = 0;
                    if (lane == leader) base = atomicAdd(&scnt[q], __popc(mm));
                    base = __shfl_sync(0xffffffffu, base, leader);
                    if (fs[jc]) {
                        const int o = base + __popc(mm & lmask);
                        if (o < CCAP) sci[q][o] = p + jc * 32;
                    }
                }
            }
        }
    }
    __syncthreads();

    // ---- pass 3: exact lex (d2, idx) selection + gather + GEMV
    if (w < QPB) {
        const int q = w;
        const int pair = pair0 + q;
        const float kx = skp[q][0], ky = skp[q][1], kz = skp[q][2];
        int cnt = scnt[q]; if (cnt > CCAP) cnt = CCAP;

        float md = INF; int mi = 0x7fffffff;
        if (lane < cnt) {
            mi = sci[q][lane];
            const float4 v = pp[mi];
            const float dx = v.x - kx, dy = v.y - ky, dz = v.z - kz;
            md = fmaf(dx, dx, fmaf(dy, dy, dz * dz));
        }
#pragma unroll
        for (int kk = 2; kk <= 32; kk <<= 1) {
#pragma unroll
            for (int j = kk >> 1; j > 0; j >>= 1) {
                const float od = __shfl_xor_sync(0xffffffffu, md, j);
                const int   oi = __shfl_xor_sync(0xffffffffu, mi, j);
                const bool asc = ((lane & kk) == 0);
                const bool low = ((lane & j) == 0);
                const bool oLess = (od < md) || (od == md && oi < mi);
                const bool takeOther = (low == asc) ? oLess : !oLess;
                if (takeOther) { md = od; mi = oi; }
            }
        }
        float mtd = __shfl_sync(0xffffffffu, md, KNN_K - 1);
        int   mti = __shfl_sync(0xffffffffu, mi, KNN_K - 1);

        for (int base0 = 32; base0 < cnt; base0 += 32) {
            const int jjx = base0 + lane;
            float cd2 = INF; int ci2 = 0x7fffffff;
            if (jjx < cnt) {
                ci2 = sci[q][jjx];
                const float4 v = pp[ci2];
                const float dx = v.x - kx, dy = v.y - ky, dz = v.z - kz;
                cd2 = fmaf(dx, dx, fmaf(dy, dy, dz * dz));
            }
#pragma unroll
            for (int kk = 2; kk <= 32; kk <<= 1) {
#pragma unroll
                for (int j = kk >> 1; j > 0; j >>= 1) {
                    const float od = __shfl_xor_sync(0xffffffffu, cd2, j);
                    const int   oi = __shfl_xor_sync(0xffffffffu, ci2, j);
                    const bool asc = ((lane & kk) == 0);
                    const bool low = ((lane & j) == 0);
                    const bool oLess = (od < cd2) || (od == cd2 && oi < ci2);
                    const bool takeOther = (low == asc) ? oLess : !oLess;
                    if (takeOther) { cd2 = od; ci2 = oi; }
                }
            }
            for (int e = 0; e < 32; ++e) {
                const float dc = __shfl_sync(0xffffffffu, cd2, e);
                const int   ic = __shfl_sync(0xffffffffu, ci2, e);
                if (!(dc < mtd || (dc == mtd && ic < mti))) break;
                float pd = __shfl_up_sync(0xffffffffu, md, 1);
                int   pi = __shfl_up_sync(0xffffffffu, mi, 1);
                if (lane == 0) { pd = -INF; pi = -1; }
                const bool disp = (dc < md) || (dc == md && ic < mi);
                if (disp) {
                    const bool tp = (pd > dc) || (pd == dc && pi > ic);
                    md = tp ? pd : dc;
                    mi = tp ? pi : ic;
                }
                mtd = __shfl_sync(0xffffffffu, md, KNN_K - 1);
                mti = __shfl_sync(0xffffffffu, mi, KNN_K - 1);
            }
        }

        const float* fbase = f + (size_t)b * NPTS * C;
        float acc = 0.f;
#pragma unroll
        for (int r = 0; r < KNN_K; ++r) {
            const int id = __shfl_sync(0xffffffffu, mi, r);
            acc += fbase[(size_t)id * C + lane];
        }
        acc *= (1.0f / KNN_K);

        float o = 0.f;
#pragma unroll
        for (int c = 0; c < C; ++c)
            o = fmaf(__shfl_sync(0xffffffffu, acc, c), sWE[c * C + lane], o);

        out[(size_t)pair * C + lane] = o;
    }
}

// ---------------------------------------------------------------------------
// Inputs: feature, pos, W_pool (dead code), W_regress, W_extract, bs.
// ---------------------------------------------------------------------------
extern "C" void kernel_launch(void* const* d_in, const int* in_sizes, int n_in,
                              void* d_out, int out_size)
{
    (void)in_sizes; (void)n_in; (void)out_size;
    const float* f    = (const float*)d_in[0];
    const float* pos  = (const float*)d_in[1];
    const float* Wreg = (const float*)d_in[3];
    const float* WE   = (const float*)d_in[4];
    float* out = (float*)d_out;

    static int attr_set = 0;
    if (!attr_set) {
        cudaFuncSetAttribute(regress_kernel,
                             cudaFuncAttributeMaxDynamicSharedMemorySize, SMEM_DYN);
        attr_set = 1;
    }
    dim3 g1(NPTS / 128, 2, BS);
    regress_kernel<<<g1, 256, SMEM_DYN>>>(f, pos, Wreg);
    knn_extract_kernel<<<BS * K / QPB, 256>>>(f, WE, out);
}